// round 1
// baseline (speedup 1.0000x reference)
#include <cuda_runtime.h>
#include <cstdint>
#include <cstddef>

// ---------------------------------------------------------------------------
// SelfAttention: qkv = x@w_attn ; RoPE(q,k) ; GQA softmax attention ; y@w_proj
// B=2 T=2048 C=2048, 16 heads, 4 kv groups, head 128. All fp32 using packed
// fma.rn.f32x2 (sm_103a) for 2x FP32 throughput.
// ---------------------------------------------------------------------------

#define Tn     2048
#define Cn     2048
#define QKVW   3072          // (16 + 2*4) * 128
#define ROWS   4096          // B*T
#define HEADS  16
#define HS     128
#define GROUPS 4

__device__ float g_qkv[ROWS * QKVW];   // 50.3 MB scratch
__device__ float g_y[ROWS * Cn];       // 33.6 MB scratch

// 1/sqrt(128) * log2(e): fold softmax scale + exp->exp2 conversion into Q
#define QK_SCALE (0.08838834764831845f * 1.4426950408889634f)

// ---- packed f32x2 helpers -------------------------------------------------
__device__ __forceinline__ unsigned long long pkb(float x) {
    unsigned long long r;
    unsigned int u = __float_as_uint(x);
    asm("mov.b64 %0, {%1, %1};" : "=l"(r) : "r"(u));
    return r;
}
__device__ __forceinline__ unsigned long long pk2(float x, float y) {
    unsigned long long r;
    unsigned int a = __float_as_uint(x), b = __float_as_uint(y);
    asm("mov.b64 %0, {%1, %2};" : "=l"(r) : "r"(a), "r"(b));
    return r;
}
__device__ __forceinline__ float2 upk(unsigned long long v) {
    unsigned int lo, hi;
    asm("mov.b64 {%0, %1}, %2;" : "=r"(lo), "=r"(hi) : "l"(v));
    return make_float2(__uint_as_float(lo), __uint_as_float(hi));
}
__device__ __forceinline__ void fma2(unsigned long long& d,
                                     unsigned long long a,
                                     unsigned long long b) {
    asm("fma.rn.f32x2 %0, %1, %2, %0;" : "+l"(d) : "l"(a), "l"(b));
}
__device__ __forceinline__ void mul2(unsigned long long& d, unsigned long long a) {
    asm("mul.rn.f32x2 %0, %0, %1;" : "+l"(d) : "l"(a));
}
__device__ __forceinline__ float ex2f(float x) {
    float r;
    asm("ex2.approx.ftz.f32 %0, %1;" : "=f"(r) : "f"(x));
    return r;
}

// ---------------------------------------------------------------------------
// Generic fp32 GEMM: C[M,N] = A[M,K] @ B[K,N], row-major, M/N mult of 128,
// K mult of 8. 128x128 block tile, 256 threads, 8x8 microtile, f32x2 packed.
// ---------------------------------------------------------------------------
template<int N, int K>
__device__ __forceinline__ void gemm_body(const float* __restrict__ A,
                                          const float* __restrict__ B,
                                          float* __restrict__ C) {
    __shared__ float As[8][132];   // As[k][m] (transposed, padded)
    __shared__ float Bs[8][128];   // Bs[k][n]

    const int tid = threadIdx.x;
    const int tx = tid & 15, ty = tid >> 4;
    const int m0 = blockIdx.y * 128, n0 = blockIdx.x * 128;

    // A load: each thread loads 4 rows at one k; STS.128 down one As row.
    const int ak = tid & 7;
    const int ar = (tid >> 3) << 2;
    // B load: one float4 of one row.
    const int bk = tid >> 5;
    const int bc = (tid & 31) << 2;

    const float* Ap = A + (size_t)(m0 + ar) * K + ak;
    const float* Bp = B + (size_t)bk * N + n0 + bc;

    unsigned long long acc[8][4];
#pragma unroll
    for (int i = 0; i < 8; i++)
#pragma unroll
        for (int j = 0; j < 4; j++) acc[i][j] = 0ull;

    float pa0 = Ap[0], pa1 = Ap[K], pa2 = Ap[2 * K], pa3 = Ap[3 * K];
    float4 pbv = *reinterpret_cast<const float4*>(Bp);

    for (int k0 = 0; k0 < K; k0 += 8) {
        *reinterpret_cast<float4*>(&As[ak][ar]) = make_float4(pa0, pa1, pa2, pa3);
        *reinterpret_cast<float4*>(&Bs[bk][bc]) = pbv;
        __syncthreads();

        if (k0 + 8 < K) {   // prefetch next tile into registers
            const float* An = Ap + k0 + 8;
            pa0 = An[0]; pa1 = An[K]; pa2 = An[2 * K]; pa3 = An[3 * K];
            pbv = *reinterpret_cast<const float4*>(Bp + (size_t)(k0 + 8) * N);
        }

#pragma unroll
        for (int kk = 0; kk < 8; kk++) {
            float4 a0 = *reinterpret_cast<const float4*>(&As[kk][ty * 8]);
            float4 a1 = *reinterpret_cast<const float4*>(&As[kk][ty * 8 + 4]);
            const ulonglong2* br =
                reinterpret_cast<const ulonglong2*>(&Bs[kk][tx * 8]);
            ulonglong2 b0 = br[0], b1 = br[1];
            unsigned long long bb[4] = {b0.x, b0.y, b1.x, b1.y};
            unsigned long long aa[8] = {pkb(a0.x), pkb(a0.y), pkb(a0.z), pkb(a0.w),
                                        pkb(a1.x), pkb(a1.y), pkb(a1.z), pkb(a1.w)};
#pragma unroll
            for (int i = 0; i < 8; i++)
#pragma unroll
                for (int j = 0; j < 4; j++) fma2(acc[i][j], aa[i], bb[j]);
        }
        __syncthreads();
    }

#pragma unroll
    for (int i = 0; i < 8; i++) {
        float* cp = C + (size_t)(m0 + ty * 8 + i) * N + n0 + tx * 8;
        ulonglong2 v0, v1;
        v0.x = acc[i][0]; v0.y = acc[i][1];
        v1.x = acc[i][2]; v1.y = acc[i][3];
        *reinterpret_cast<ulonglong2*>(cp) = v0;
        *reinterpret_cast<ulonglong2*>(cp + 4) = v1;
    }
}

__global__ __launch_bounds__(256, 2) void gemm1_kernel(const float* __restrict__ x,
                                                       const float* __restrict__ w) {
    gemm_body<QKVW, Cn>(x, w, g_qkv);
}
__global__ __launch_bounds__(256, 2) void gemm2_kernel(const float* __restrict__ w,
                                                       float* __restrict__ out) {
    gemm_body<Cn, Cn>(g_y, w, out);
}

// ---------------------------------------------------------------------------
// RoPE in place on q (slots 0..3, scaled by QK_SCALE) and k (slot 4).
// qkv row layout: [group 0..3][slot 0..5][128]
// ---------------------------------------------------------------------------
__global__ __launch_bounds__(256) void rope_kernel(const float* __restrict__ cosb,
                                                   const float* __restrict__ sinb) {
    int idx = blockIdx.x * 256 + threadIdx.x;     // < 4096*4*5*64
    int d = idx & 63;
    int rg = idx >> 6;
    int slot = rg % 5;
    int q = rg / 5;
    int g = q & 3;
    int row = q >> 2;
    int t = row & (Tn - 1);

    float* p = g_qkv + (size_t)row * QKVW + g * 768 + slot * 128 + d;
    float x1 = p[0], x2 = p[64];
    float c = cosb[t * 64 + d], s = sinb[t * 64 + d];
    float o1 = x1 * c - x2 * s;
    float o2 = x1 * s + x2 * c;
    if (slot < 4) { o1 *= QK_SCALE; o2 *= QK_SCALE; }
    p[0] = o1;
    p[64] = o2;
}

// ---------------------------------------------------------------------------
// Flash attention. One CTA per (qblock, head, b). 256 threads, 8 warps.
// Smem: Qs[d][i] (transposed, 132 pad), KPs (K transposed -> then P[i][j]),
// Vs[j][d] natural. 192 KB dynamic smem -> 1 CTA/SM.
// ---------------------------------------------------------------------------
#define ATT_SMEM ((128 * 132 * 2 + 128 * 128) * 4)

__global__ __launch_bounds__(256, 1) void attn_kernel() {
    extern __shared__ float sm[];
    float* Qs  = sm;                  // [128][132]  Qs[d*132 + i] = Q[i][d]
    float* KPs = sm + 128 * 132;      // [128][132]  K transposed, then P[i][j]
    float* Vs  = sm + 2 * 128 * 132;  // [128][128]  Vs[j*128 + d]

    const int tid = threadIdx.x;
    const int tx = tid & 15, ty = tid >> 4;
    const int qb = blockIdx.x, h = blockIdx.y, b = blockIdx.z;
    const int g = h >> 2;
    const int qcol = g * 768 + (h & 3) * 128;
    const int kcol = g * 768 + 512;
    const int vcol = kcol + 128;

    const float* Qg = g_qkv + (size_t)(b * Tn + qb * 128) * QKVW + qcol;

    // load Q transposed: thread handles 4 consecutive rows at one d
#pragma unroll
    for (int rep = 0; rep < 16; rep++) {
        int idx = rep * 256 + tid;
        int d = idx & 127;
        int r0 = (idx >> 7) << 2;
        float4 v;
        v.x = Qg[(r0 + 0) * QKVW + d];
        v.y = Qg[(r0 + 1) * QKVW + d];
        v.z = Qg[(r0 + 2) * QKVW + d];
        v.w = Qg[(r0 + 3) * QKVW + d];
        *reinterpret_cast<float4*>(&Qs[d * 132 + r0]) = v;
    }

    unsigned long long o2[8][4];
    float m_i[8], l_i[8];
#pragma unroll
    for (int i = 0; i < 8; i++) {
        m_i[i] = __int_as_float(0xff800000);   // -inf
        l_i[i] = 0.f;
#pragma unroll
        for (int j = 0; j < 4; j++) o2[i][j] = 0ull;
    }

#pragma unroll 1
    for (int kt = 0; kt < 16; kt++) {
        __syncthreads();   // prev O-GEMM done reading KPs/Vs; Qs visible on kt=0
        const float* Kg = g_qkv + (size_t)(b * Tn + kt * 128) * QKVW + kcol;
        const float* Vg = g_qkv + (size_t)(b * Tn + kt * 128) * QKVW + vcol;
#pragma unroll
        for (int rep = 0; rep < 16; rep++) {
            int idx = rep * 256 + tid;
            int d = idx & 127;
            int r0 = (idx >> 7) << 2;
            float4 v;
            v.x = Kg[(r0 + 0) * QKVW + d];
            v.y = Kg[(r0 + 1) * QKVW + d];
            v.z = Kg[(r0 + 2) * QKVW + d];
            v.w = Kg[(r0 + 3) * QKVW + d];
            *reinterpret_cast<float4*>(&KPs[d * 132 + r0]) = v;
        }
#pragma unroll
        for (int rep = 0; rep < 16; rep++) {
            int idx = (rep * 256 + tid) * 4;
            int r = idx >> 7;
            int c = idx & 127;
            *reinterpret_cast<float4*>(&Vs[r * 128 + c]) =
                *reinterpret_cast<const float4*>(&Vg[(size_t)r * QKVW + c]);
        }
        __syncthreads();

        // ---- S = Q K^T (packed along j) ----
        unsigned long long s2[8][4];
#pragma unroll
        for (int i = 0; i < 8; i++)
#pragma unroll
            for (int j = 0; j < 4; j++) s2[i][j] = 0ull;

#pragma unroll 4
        for (int d = 0; d < 128; d++) {
            float4 a0 = *reinterpret_cast<const float4*>(&Qs[d * 132 + ty * 8]);
            float4 a1 = *reinterpret_cast<const float4*>(&Qs[d * 132 + ty * 8 + 4]);
            const ulonglong2* kr =
                reinterpret_cast<const ulonglong2*>(&KPs[d * 132 + tx * 8]);
            ulonglong2 b0 = kr[0], b1 = kr[1];
            unsigned long long bb[4] = {b0.x, b0.y, b1.x, b1.y};
            unsigned long long aa[8] = {pkb(a0.x), pkb(a0.y), pkb(a0.z), pkb(a0.w),
                                        pkb(a1.x), pkb(a1.y), pkb(a1.z), pkb(a1.w)};
#pragma unroll
            for (int i = 0; i < 8; i++)
#pragma unroll
                for (int j = 0; j < 4; j++) fma2(s2[i][j], aa[i], bb[j]);
        }
        __syncthreads();   // everyone done reading KPs -> safe to overwrite with P

        // ---- online softmax (rows owned by 16 lanes sharing ty) ----
#pragma unroll
        for (int ii = 0; ii < 8; ii++) {
            float v[8];
#pragma unroll
            for (int j = 0; j < 4; j++) {
                float2 t2 = upk(s2[ii][j]);
                v[2 * j] = t2.x;
                v[2 * j + 1] = t2.y;
            }
            float rmax = v[0];
#pragma unroll
            for (int j = 1; j < 8; j++) rmax = fmaxf(rmax, v[j]);
#pragma unroll
            for (int off = 1; off < 16; off <<= 1)
                rmax = fmaxf(rmax, __shfl_xor_sync(0xffffffffu, rmax, off));
            float mnew = fmaxf(m_i[ii], rmax);
            float corr = ex2f(m_i[ii] - mnew);
            m_i[ii] = mnew;
            float rsum = 0.f;
#pragma unroll
            for (int j = 0; j < 8; j++) {
                v[j] = ex2f(v[j] - mnew);
                rsum += v[j];
            }
#pragma unroll
            for (int off = 1; off < 16; off <<= 1)
                rsum += __shfl_xor_sync(0xffffffffu, rsum, off);
            l_i[ii] = l_i[ii] * corr + rsum;
            unsigned long long c2 = pk2(corr, corr);
#pragma unroll
            for (int j = 0; j < 4; j++) mul2(o2[ii][j], c2);

            float* prow = &KPs[(ty * 8 + ii) * 132 + tx * 8];
            *reinterpret_cast<float4*>(prow) = make_float4(v[0], v[1], v[2], v[3]);
            *reinterpret_cast<float4*>(prow + 4) = make_float4(v[4], v[5], v[6], v[7]);
        }
        __syncthreads();   // P visible

        // ---- O += P @ V ----
#pragma unroll 2
        for (int j = 0; j < 128; j++) {
            const ulonglong2* vr =
                reinterpret_cast<const ulonglong2*>(&Vs[j * 128 + tx * 8]);
            ulonglong2 b0 = vr[0], b1 = vr[1];
            unsigned long long bb[4] = {b0.x, b0.y, b1.x, b1.y};
#pragma unroll
            for (int ii = 0; ii < 8; ii++) {
                unsigned long long a2 = pkb(KPs[(ty * 8 + ii) * 132 + j]);
                fma2(o2[ii][0], a2, bb[0]);
                fma2(o2[ii][1], a2, bb[1]);
                fma2(o2[ii][2], a2, bb[2]);
                fma2(o2[ii][3], a2, bb[3]);
            }
        }
    }

    // ---- epilogue: y[b*T + row, h*128 + d] = O / l ----
#pragma unroll
    for (int ii = 0; ii < 8; ii++) {
        float inv = 1.0f / l_i[ii];
        float2 r0 = upk(o2[ii][0]);
        float2 r1 = upk(o2[ii][1]);
        float2 r2 = upk(o2[ii][2]);
        float2 r3 = upk(o2[ii][3]);
        int row = b * Tn + qb * 128 + ty * 8 + ii;
        float* yp = g_y + (size_t)row * Cn + h * 128 + tx * 8;
        *reinterpret_cast<float4*>(yp) =
            make_float4(r0.x * inv, r0.y * inv, r1.x * inv, r1.y * inv);
        *reinterpret_cast<float4*>(yp + 4) =
            make_float4(r2.x * inv, r2.y * inv, r3.x * inv, r3.y * inv);
    }
}

// ---------------------------------------------------------------------------
extern "C" void kernel_launch(void* const* d_in, const int* in_sizes, int n_in,
                              void* d_out, int out_size) {
    const float* x      = (const float*)d_in[0];
    const float* cosb   = (const float*)d_in[1];
    const float* sinb   = (const float*)d_in[2];
    const float* w_attn = (const float*)d_in[3];
    const float* w_proj = (const float*)d_in[4];
    float* out = (float*)d_out;

    (void)in_sizes; (void)n_in; (void)out_size;

    (void)cudaFuncSetAttribute(attn_kernel,
                               cudaFuncAttributeMaxDynamicSharedMemorySize,
                               ATT_SMEM);

    // 1. qkv = x @ w_attn
    gemm1_kernel<<<dim3(QKVW / 128, ROWS / 128), 256>>>(x, w_attn);
    // 2. RoPE on q (with scale*log2e folded) and k
    rope_kernel<<<(ROWS * GROUPS * 5 * 64) / 256, 256>>>(cosb, sinb);
    // 3. attention -> g_y
    attn_kernel<<<dim3(Tn / 128, HEADS, 2), 256, ATT_SMEM>>>();
    // 4. out = y @ w_proj
    gemm2_kernel<<<dim3(Cn / 128, ROWS / 128), 256>>>(w_proj, out);
}

// round 4
// speedup vs baseline: 2.3679x; 2.3679x over previous
#include <cuda_runtime.h>
#include <cuda_bf16.h>
#include <cstdint>
#include <cstddef>

// ---------------------------------------------------------------------------
// SelfAttention on sm_103 via baseline-PTX tensor cores (mma.sync bf16 x3).
// Build target is compute_103 (no 'a'): tcgen05/TMEM/TMA unavailable.
// All GEMM-like work: mma.sync.m16n8k16 bf16 with hi/lo split compensation.
// R3 fix: hgemm3 cp.async loader covered only half of each k-chunk row
// (2x16B at offsets {0,32} of a 64B row) -> uninitialized smem -> NaN.
// Now 4x16B per row via two CP16 per thread per operand.
// ---------------------------------------------------------------------------

#define Tn     2048
#define Cn     2048
#define QKVW   3072          // (16 + 2*4) * 128
#define ROWS   4096          // B*T
#define GK     2048          // K dim of both big GEMMs

typedef __nv_bfloat16 bf16;

__device__ __align__(16) float g_qkv[(size_t)ROWS * QKVW];
__device__ __align__(16) bf16  g_xh[(size_t)ROWS * GK];
__device__ __align__(16) bf16  g_xl[(size_t)ROWS * GK];
__device__ __align__(16) bf16  g_wah[(size_t)QKVW * GK];
__device__ __align__(16) bf16  g_wal[(size_t)QKVW * GK];
__device__ __align__(16) bf16  g_wph[(size_t)Cn * GK];
__device__ __align__(16) bf16  g_wpl[(size_t)Cn * GK];
__device__ __align__(16) bf16  g_qh[(size_t)2 * 16 * Tn * 128];
__device__ __align__(16) bf16  g_ql[(size_t)2 * 16 * Tn * 128];
__device__ __align__(16) bf16  g_kh[(size_t)2 * 4 * Tn * 128];
__device__ __align__(16) bf16  g_kl[(size_t)2 * 4 * Tn * 128];
__device__ __align__(16) bf16  g_vth[(size_t)2 * 4 * 128 * Tn];
__device__ __align__(16) bf16  g_vtl[(size_t)2 * 4 * 128 * Tn];
__device__ __align__(16) bf16  g_yh[(size_t)ROWS * Cn];
__device__ __align__(16) bf16  g_yl[(size_t)ROWS * Cn];

// 1/sqrt(128) * log2(e): softmax scale + exp->exp2, folded into q
#define QK_SCALE (0.08838834764831845f * 1.4426950408889634f)

// ============================ helpers =======================================
__device__ __forceinline__ float ex2f(float x) {
    float r;
    asm("ex2.approx.ftz.f32 %0, %1;" : "=f"(r) : "f"(x));
    return r;
}
// pack two fp32 -> bf16x2 reg; 'lo' arg goes to bits [15:0]
__device__ __forceinline__ uint32_t pkbf2(float lo, float hi) {
    uint32_t r;
    asm("cvt.rn.bf16x2.f32 %0, %1, %2;" : "=r"(r) : "f"(hi), "f"(lo));
    return r;
}
__device__ __forceinline__ void mma_bf16(float (&d)[4], const uint32_t (&a)[4],
                                         const uint32_t (&b)[2]) {
    asm volatile(
        "mma.sync.aligned.m16n8k16.row.col.f32.bf16.bf16.f32 "
        "{%0,%1,%2,%3}, {%4,%5,%6,%7}, {%8,%9}, {%0,%1,%2,%3};"
        : "+f"(d[0]), "+f"(d[1]), "+f"(d[2]), "+f"(d[3])
        : "r"(a[0]), "r"(a[1]), "r"(a[2]), "r"(a[3]), "r"(b[0]), "r"(b[1]));
}
__device__ __forceinline__ uint32_t smem_u32(const void* p) {
    uint32_t a;
    asm("{ .reg .u64 t; cvta.to.shared.u64 t, %1; cvt.u32.u64 %0, t; }"
        : "=r"(a) : "l"(p));
    return a;
}
#define CP16(dst, src) \
    asm volatile("cp.async.cg.shared.global [%0], [%1], 16;" \
                 :: "r"(dst), "l"(src) : "memory")
#define CPCOMMIT() asm volatile("cp.async.commit_group;" ::: "memory")
#define CPWAIT1()  asm volatile("cp.async.wait_group 1;" ::: "memory")
#define CPWAIT0()  asm volatile("cp.async.wait_group 0;" ::: "memory")

// ---------------------------------------------------------------------------
// split x -> bf16 hi/lo (grid-stride over float4)
// ---------------------------------------------------------------------------
__global__ __launch_bounds__(256) void splitx_kernel(const float* __restrict__ x) {
    size_t i = ((size_t)blockIdx.x * 256 + threadIdx.x) * 4;
    float4 v = *(const float4*)(x + i);
    uint32_t h0 = pkbf2(v.x, v.y), h1 = pkbf2(v.z, v.w);
    float e0 = v.x - __uint_as_float(h0 << 16);
    float e1 = v.y - __uint_as_float(h0 & 0xffff0000u);
    float e2 = v.z - __uint_as_float(h1 << 16);
    float e3 = v.w - __uint_as_float(h1 & 0xffff0000u);
    *(uint2*)(g_xh + i) = make_uint2(h0, h1);
    *(uint2*)(g_xl + i) = make_uint2(pkbf2(e0, e1), pkbf2(e2, e3));
}

// ---------------------------------------------------------------------------
// transpose + split weights: in [2048][Ccols] fp32 -> hi/lo [Ccols][2048] bf16
// ---------------------------------------------------------------------------
__global__ __launch_bounds__(256) void wsplit_kernel(
    const float* __restrict__ in, bf16* __restrict__ hi, bf16* __restrict__ lo,
    int Ccols)
{
    __shared__ float tb[32][33];
    const int bx = blockIdx.x * 32, by = blockIdx.y * 32;
    const int tx = threadIdx.x, ty = threadIdx.y;
#pragma unroll
    for (int j = 0; j < 32; j += 8)
        tb[ty + j][tx] = in[(size_t)(by + ty + j) * Ccols + bx + tx];
    __syncthreads();
#pragma unroll
    for (int j = 0; j < 32; j += 8) {
        float v = tb[tx][ty + j];
        size_t o = (size_t)(bx + ty + j) * GK + by + tx;
        bf16 h = __float2bfloat16(v);
        hi[o] = h;
        lo[o] = __float2bfloat16(v - __bfloat162float(h));
    }
}

// ---------------------------------------------------------------------------
// bf16x3 GEMM: C[M,N] = A[M,2048] @ BT[N,2048]^T.  A,BT given as hi/lo bf16.
// 128x128 CTA tile, kchunk 32, cp.async double buffer, 8 warps (4m x 2n),
// warp tile 32x64, direct-LDS fragments (80B row stride, conflict-free).
// ---------------------------------------------------------------------------
#define GS_STAGE 40960
#define GSM (2 * GS_STAGE)

__global__ __launch_bounds__(256, 2) void hgemm3_kernel(
    const bf16* __restrict__ Ah, const bf16* __restrict__ Al,
    const bf16* __restrict__ Bh, const bf16* __restrict__ Bl,
    float* __restrict__ C, int N)
{
    extern __shared__ char sm[];
    const uint32_t sb = smem_u32(sm);
    const int tid = threadIdx.x;
    const int lane = tid & 31, wid = tid >> 5;
    const int lg = lane >> 2, tq = lane & 3;
    const int mi = wid & 3, ni = wid >> 2;
    const size_t m0 = (size_t)blockIdx.y * 128, n0 = (size_t)blockIdx.x * 128;

    // per-thread global->smem: 2 x 16B per operand per stage (full 64B rows)
    const int lr = tid >> 1, lh = tid & 1;
    const bf16* pAh = Ah + (m0 + lr) * GK + lh * 16;
    const bf16* pAl = Al + (m0 + lr) * GK + lh * 16;
    const bf16* pBh = Bh + (n0 + lr) * GK + lh * 16;
    const bf16* pBl = Bl + (n0 + lr) * GK + lh * 16;
    const uint32_t sdst = sb + lr * 80 + lh * 32;

    float c[2][8][4];
#pragma unroll
    for (int a = 0; a < 2; a++)
#pragma unroll
        for (int b = 0; b < 8; b++)
#pragma unroll
            for (int d = 0; d < 4; d++) c[a][b][d] = 0.f;

    // stage 0
    {
        uint32_t d0 = sdst;
        CP16(d0,              pAh);
        CP16(d0 + 16,         pAh + 8);
        CP16(d0 + 10240,      pAl);
        CP16(d0 + 10240 + 16, pAl + 8);
        CP16(d0 + 20480,      pBh);
        CP16(d0 + 20480 + 16, pBh + 8);
        CP16(d0 + 30720,      pBl);
        CP16(d0 + 30720 + 16, pBl + 8);
        CPCOMMIT();
    }

#pragma unroll 1
    for (int kt = 0; kt < GK / 32; kt++) {
        const int s = kt & 1;
        if (kt + 1 < GK / 32) {
            uint32_t d0 = sdst + (s ^ 1) * GS_STAGE;
            size_t off = (size_t)(kt + 1) * 32;
            CP16(d0,              pAh + off);
            CP16(d0 + 16,         pAh + off + 8);
            CP16(d0 + 10240,      pAl + off);
            CP16(d0 + 10240 + 16, pAl + off + 8);
            CP16(d0 + 20480,      pBh + off);
            CP16(d0 + 20480 + 16, pBh + off + 8);
            CP16(d0 + 30720,      pBl + off);
            CP16(d0 + 30720 + 16, pBl + off + 8);
            CPCOMMIT();
            CPWAIT1();
        } else {
            CPWAIT0();
        }
        __syncthreads();

        const char* base = sm + s * GS_STAGE;
#pragma unroll
        for (int kk = 0; kk < 2; kk++) {
            uint32_t ah[2][4], al[2][4];
#pragma unroll
            for (int mt = 0; mt < 2; mt++) {
                const char* ar = base + (mi * 32 + mt * 16 + lg) * 80 + kk * 32 + tq * 4;
                ah[mt][0] = *(const uint32_t*)(ar);
                ah[mt][1] = *(const uint32_t*)(ar + 8 * 80);
                ah[mt][2] = *(const uint32_t*)(ar + 16);
                ah[mt][3] = *(const uint32_t*)(ar + 8 * 80 + 16);
                al[mt][0] = *(const uint32_t*)(ar + 10240);
                al[mt][1] = *(const uint32_t*)(ar + 10240 + 8 * 80);
                al[mt][2] = *(const uint32_t*)(ar + 10240 + 16);
                al[mt][3] = *(const uint32_t*)(ar + 10240 + 8 * 80 + 16);
            }
#pragma unroll
            for (int nt = 0; nt < 8; nt++) {
                const char* br = base + 20480 + (ni * 64 + nt * 8 + lg) * 80 + kk * 32 + tq * 4;
                uint32_t bh[2] = { *(const uint32_t*)br, *(const uint32_t*)(br + 16) };
                uint32_t bl[2] = { *(const uint32_t*)(br + 10240),
                                   *(const uint32_t*)(br + 10240 + 16) };
#pragma unroll
                for (int mt = 0; mt < 2; mt++) {
                    mma_bf16(c[mt][nt], ah[mt], bh);
                    mma_bf16(c[mt][nt], ah[mt], bl);
                    mma_bf16(c[mt][nt], al[mt], bh);
                }
            }
        }
        __syncthreads();
    }

#pragma unroll
    for (int mt = 0; mt < 2; mt++) {
        size_t r0 = m0 + mi * 32 + mt * 16 + lg;
#pragma unroll
        for (int nt = 0; nt < 8; nt++) {
            size_t col = n0 + ni * 64 + nt * 8 + tq * 2;
            *(float2*)(C + r0 * N + col)       = make_float2(c[mt][nt][0], c[mt][nt][1]);
            *(float2*)(C + (r0 + 8) * N + col) = make_float2(c[mt][nt][2], c[mt][nt][3]);
        }
    }
}

// ---------------------------------------------------------------------------
// RoPE + bf16 split: q (slots 0-3, scaled) -> g_qh/ql [b][h][t][d];
// k (slot 4) -> g_kh/kl [b][g][t][d]
// ---------------------------------------------------------------------------
__global__ __launch_bounds__(256) void rope_split_kernel(
    const float* __restrict__ cosb, const float* __restrict__ sinb)
{
    int idx = blockIdx.x * 256 + threadIdx.x;     // ROWS*4*5*64
    int d = idx & 63;
    int rg = idx >> 6;
    int slot = rg % 5;
    int q5 = rg / 5;
    int grp = q5 & 3;
    int row = q5 >> 2;
    int b = row >> 11, t = row & (Tn - 1);

    const float* p = g_qkv + (size_t)row * QKVW + grp * 768 + slot * 128 + d;
    float x1 = p[0], x2 = p[64];
    float cc = cosb[t * 64 + d], ss = sinb[t * 64 + d];
    float o1 = x1 * cc - x2 * ss;
    float o2 = x1 * ss + x2 * cc;

    bf16 *dh, *dl;
    size_t base;
    if (slot < 4) {
        o1 *= QK_SCALE; o2 *= QK_SCALE;
        int head = grp * 4 + slot;
        base = ((size_t)(b * 16 + head) * Tn + t) * 128 + d;
        dh = g_qh; dl = g_ql;
    } else {
        base = ((size_t)(b * 4 + grp) * Tn + t) * 128 + d;
        dh = g_kh; dl = g_kl;
    }
    bf16 h1 = __float2bfloat16(o1), h2 = __float2bfloat16(o2);
    dh[base]      = h1;
    dh[base + 64] = h2;
    dl[base]      = __float2bfloat16(o1 - __bfloat162float(h1));
    dl[base + 64] = __float2bfloat16(o2 - __bfloat162float(h2));
}

// ---------------------------------------------------------------------------
// v: split + transpose -> g_vth/vtl [b][g][d][t]
// ---------------------------------------------------------------------------
__global__ __launch_bounds__(256) void vsplit_kernel() {
    __shared__ float tb[32][33];
    const int bg = blockIdx.z;
    const int t0 = blockIdx.x * 32, d0 = blockIdx.y * 32;
    const int tx = threadIdx.x, ty = threadIdx.y;
    const int b = bg >> 2, grp = bg & 3;
#pragma unroll
    for (int j = 0; j < 32; j += 8)
        tb[ty + j][tx] = g_qkv[((size_t)b * Tn + t0 + ty + j) * QKVW +
                               grp * 768 + 640 + d0 + tx];
    __syncthreads();
#pragma unroll
    for (int j = 0; j < 32; j += 8) {
        float v = tb[tx][ty + j];
        size_t o = ((size_t)bg * 128 + d0 + ty + j) * Tn + t0 + tx;
        bf16 h = __float2bfloat16(v);
        g_vth[o] = h;
        g_vtl[o] = __float2bfloat16(v - __bfloat162float(h));
    }
}

// ---------------------------------------------------------------------------
// Flash attention on mma.sync bf16x3.
// CTA = (qb, h, b): 128 q rows, 8 warps x m16. Key tiles of 64.
// smem: Qh/Ql [128 rows x 272B], Kh/Kl [64 x 272B], Vth/Vtl [128 d x 144B].
// ---------------------------------------------------------------------------
#define AQ_H 0
#define AQ_L 34816
#define AK_H 69632
#define AK_L 87040
#define AV_H 104448
#define AV_L 122880
#define ATT_SMEM 141312

__global__ __launch_bounds__(256, 1) void attn_kernel() {
    extern __shared__ char sm[];
    const int tid = threadIdx.x;
    const int lane = tid & 31, wid = tid >> 5;
    const int lg = lane >> 2, tq = lane & 3;
    const int qb = blockIdx.x, h = blockIdx.y, b = blockIdx.z;
    const int grp = h >> 2;

    // load Q (hi/lo), 128 x 128 bf16 each
    {
        const bf16* qhp = g_qh + ((size_t)(b * 16 + h) * Tn + qb * 128) * 128;
        const bf16* qlp = g_ql + ((size_t)(b * 16 + h) * Tn + qb * 128) * 128;
#pragma unroll
        for (int it = 0; it < 8; it++) {
            int idx = it * 256 + tid;
            int r = idx >> 4, hx = idx & 15;
            *(uint4*)(sm + AQ_H + r * 272 + hx * 16) = *(const uint4*)(qhp + (size_t)r * 128 + hx * 8);
            *(uint4*)(sm + AQ_L + r * 272 + hx * 16) = *(const uint4*)(qlp + (size_t)r * 128 + hx * 8);
        }
    }

    float o[16][4];
#pragma unroll
    for (int i = 0; i < 16; i++)
#pragma unroll
        for (int j = 0; j < 4; j++) o[i][j] = 0.f;
    float m0 = __int_as_float(0xff800000), m1 = m0;
    float l0 = 0.f, l1 = 0.f;

    const bf16* khp = g_kh + (size_t)(b * 4 + grp) * Tn * 128;
    const bf16* klp = g_kl + (size_t)(b * 4 + grp) * Tn * 128;
    const bf16* vhp = g_vth + (size_t)(b * 4 + grp) * 128 * Tn;
    const bf16* vlp = g_vtl + (size_t)(b * 4 + grp) * 128 * Tn;

#pragma unroll 1
    for (int kt = 0; kt < Tn / 64; kt++) {
        __syncthreads();   // prev tile's reads done (also orders Q on kt=0)
#pragma unroll
        for (int it = 0; it < 4; it++) {
            int idx = it * 256 + tid;
            int r = idx >> 4, hx = idx & 15;
            size_t go = ((size_t)kt * 64 + r) * 128 + hx * 8;
            *(uint4*)(sm + AK_H + r * 272 + hx * 16) = *(const uint4*)(khp + go);
            *(uint4*)(sm + AK_L + r * 272 + hx * 16) = *(const uint4*)(klp + go);
        }
#pragma unroll
        for (int it = 0; it < 4; it++) {
            int idx = it * 256 + tid;
            int r = idx >> 3, hx = idx & 7;
            size_t go = (size_t)r * Tn + kt * 64 + hx * 8;
            *(uint4*)(sm + AV_H + r * 144 + hx * 16) = *(const uint4*)(vhp + go);
            *(uint4*)(sm + AV_L + r * 144 + hx * 16) = *(const uint4*)(vlp + go);
        }
        __syncthreads();

        // ---- S = Q K^T (bf16x3), warp strip m16 x n64 ----
        float s[8][4];
#pragma unroll
        for (int i = 0; i < 8; i++)
#pragma unroll
            for (int j = 0; j < 4; j++) s[i][j] = 0.f;

#pragma unroll
        for (int kk = 0; kk < 8; kk++) {
            uint32_t qah[4], qal[4];
            const char* qr = sm + AQ_H + (wid * 16 + lg) * 272 + kk * 32 + tq * 4;
            qah[0] = *(const uint32_t*)(qr);
            qah[1] = *(const uint32_t*)(qr + 8 * 272);
            qah[2] = *(const uint32_t*)(qr + 16);
            qah[3] = *(const uint32_t*)(qr + 8 * 272 + 16);
            qal[0] = *(const uint32_t*)(qr + 34816);
            qal[1] = *(const uint32_t*)(qr + 34816 + 8 * 272);
            qal[2] = *(const uint32_t*)(qr + 34816 + 16);
            qal[3] = *(const uint32_t*)(qr + 34816 + 8 * 272 + 16);
#pragma unroll
            for (int nt = 0; nt < 8; nt++) {
                const char* kr = sm + AK_H + (nt * 8 + lg) * 272 + kk * 32 + tq * 4;
                uint32_t kbh[2] = { *(const uint32_t*)kr, *(const uint32_t*)(kr + 16) };
                uint32_t kbl[2] = { *(const uint32_t*)(kr + 17408),
                                    *(const uint32_t*)(kr + 17408 + 16) };
                mma_bf16(s[nt], qah, kbh);
                mma_bf16(s[nt], qah, kbl);
                mma_bf16(s[nt], qal, kbh);
            }
        }

        // ---- online softmax (2 rows per lane: lg, lg+8) ----
        float mx0 = s[0][0], mx1 = s[0][2];
#pragma unroll
        for (int nt = 0; nt < 8; nt++) {
            mx0 = fmaxf(mx0, fmaxf(s[nt][0], s[nt][1]));
            mx1 = fmaxf(mx1, fmaxf(s[nt][2], s[nt][3]));
        }
        mx0 = fmaxf(mx0, __shfl_xor_sync(0xffffffffu, mx0, 1));
        mx0 = fmaxf(mx0, __shfl_xor_sync(0xffffffffu, mx0, 2));
        mx1 = fmaxf(mx1, __shfl_xor_sync(0xffffffffu, mx1, 1));
        mx1 = fmaxf(mx1, __shfl_xor_sync(0xffffffffu, mx1, 2));
        float mn0 = fmaxf(m0, mx0), mn1 = fmaxf(m1, mx1);
        float cr0 = ex2f(m0 - mn0), cr1 = ex2f(m1 - mn1);
        m0 = mn0; m1 = mn1;
        float sum0 = 0.f, sum1 = 0.f;
#pragma unroll
        for (int nt = 0; nt < 8; nt++) {
            s[nt][0] = ex2f(s[nt][0] - mn0);
            s[nt][1] = ex2f(s[nt][1] - mn0);
            s[nt][2] = ex2f(s[nt][2] - mn1);
            s[nt][3] = ex2f(s[nt][3] - mn1);
            sum0 += s[nt][0] + s[nt][1];
            sum1 += s[nt][2] + s[nt][3];
        }
        sum0 += __shfl_xor_sync(0xffffffffu, sum0, 1);
        sum0 += __shfl_xor_sync(0xffffffffu, sum0, 2);
        sum1 += __shfl_xor_sync(0xffffffffu, sum1, 1);
        sum1 += __shfl_xor_sync(0xffffffffu, sum1, 2);
        l0 = l0 * cr0 + sum0;
        l1 = l1 * cr1 + sum1;
#pragma unroll
        for (int nt = 0; nt < 16; nt++) {
            o[nt][0] *= cr0; o[nt][1] *= cr0;
            o[nt][2] *= cr1; o[nt][3] *= cr1;
        }

        // ---- O += P V (bf16x3); P frags straight from S accum regs ----
#pragma unroll
        for (int kk = 0; kk < 4; kk++) {
            uint32_t ph[4], pl[4];
            {
                float e0 = s[2 * kk][0], e1 = s[2 * kk][1];
                ph[0] = pkbf2(e0, e1);
                pl[0] = pkbf2(e0 - __uint_as_float(ph[0] << 16),
                              e1 - __uint_as_float(ph[0] & 0xffff0000u));
                e0 = s[2 * kk][2]; e1 = s[2 * kk][3];
                ph[1] = pkbf2(e0, e1);
                pl[1] = pkbf2(e0 - __uint_as_float(ph[1] << 16),
                              e1 - __uint_as_float(ph[1] & 0xffff0000u));
                e0 = s[2 * kk + 1][0]; e1 = s[2 * kk + 1][1];
                ph[2] = pkbf2(e0, e1);
                pl[2] = pkbf2(e0 - __uint_as_float(ph[2] << 16),
                              e1 - __uint_as_float(ph[2] & 0xffff0000u));
                e0 = s[2 * kk + 1][2]; e1 = s[2 * kk + 1][3];
                ph[3] = pkbf2(e0, e1);
                pl[3] = pkbf2(e0 - __uint_as_float(ph[3] << 16),
                              e1 - __uint_as_float(ph[3] & 0xffff0000u));
            }
#pragma unroll
            for (int nt = 0; nt < 16; nt++) {
                const char* vr = sm + AV_H + (nt * 8 + lg) * 144 + kk * 32 + tq * 4;
                uint32_t vbh[2] = { *(const uint32_t*)vr, *(const uint32_t*)(vr + 16) };
                uint32_t vbl[2] = { *(const uint32_t*)(vr + 18432),
                                    *(const uint32_t*)(vr + 18432 + 16) };
                mma_bf16(o[nt], ph, vbh);
                mma_bf16(o[nt], ph, vbl);
                mma_bf16(o[nt], pl, vbh);
            }
        }
    }

    // ---- epilogue: y = O / l, split to bf16 hi/lo ----
    float i0 = 1.f / l0, i1 = 1.f / l1;
    size_t row0 = (size_t)b * Tn + qb * 128 + wid * 16 + lg;
#pragma unroll
    for (int nt = 0; nt < 16; nt++) {
        int col = h * 128 + nt * 8 + tq * 2;
        float v0 = o[nt][0] * i0, v1 = o[nt][1] * i0;
        uint32_t hh = pkbf2(v0, v1);
        uint32_t ll = pkbf2(v0 - __uint_as_float(hh << 16),
                            v1 - __uint_as_float(hh & 0xffff0000u));
        *(uint32_t*)(g_yh + row0 * Cn + col) = hh;
        *(uint32_t*)(g_yl + row0 * Cn + col) = ll;
        v0 = o[nt][2] * i1; v1 = o[nt][3] * i1;
        hh = pkbf2(v0, v1);
        ll = pkbf2(v0 - __uint_as_float(hh << 16),
                   v1 - __uint_as_float(hh & 0xffff0000u));
        *(uint32_t*)(g_yh + (row0 + 8) * Cn + col) = hh;
        *(uint32_t*)(g_yl + (row0 + 8) * Cn + col) = ll;
    }
}

// ---------------------------------------------------------------------------
extern "C" void kernel_launch(void* const* d_in, const int* in_sizes, int n_in,
                              void* d_out, int out_size) {
    const float* x      = (const float*)d_in[0];
    const float* cosb   = (const float*)d_in[1];
    const float* sinb   = (const float*)d_in[2];
    const float* w_attn = (const float*)d_in[3];
    const float* w_proj = (const float*)d_in[4];
    float* out = (float*)d_out;
    (void)in_sizes; (void)n_in; (void)out_size;

    (void)cudaFuncSetAttribute(hgemm3_kernel,
                               cudaFuncAttributeMaxDynamicSharedMemorySize, GSM);
    (void)cudaFuncSetAttribute(attn_kernel,
                               cudaFuncAttributeMaxDynamicSharedMemorySize, ATT_SMEM);

    float* qkvp = nullptr;
    bf16 *xh, *xl, *wah, *wal, *wph, *wpl, *yh, *yl;
    (void)cudaGetSymbolAddress((void**)&qkvp, g_qkv);
    (void)cudaGetSymbolAddress((void**)&xh, g_xh);
    (void)cudaGetSymbolAddress((void**)&xl, g_xl);
    (void)cudaGetSymbolAddress((void**)&wah, g_wah);
    (void)cudaGetSymbolAddress((void**)&wal, g_wal);
    (void)cudaGetSymbolAddress((void**)&wph, g_wph);
    (void)cudaGetSymbolAddress((void**)&wpl, g_wpl);
    (void)cudaGetSymbolAddress((void**)&yh, g_yh);
    (void)cudaGetSymbolAddress((void**)&yl, g_yl);

    // 0. splits
    splitx_kernel<<<(ROWS * GK / 4) / 256, 256>>>(x);
    wsplit_kernel<<<dim3(QKVW / 32, GK / 32), dim3(32, 8)>>>(w_attn, wah, wal, QKVW);
    wsplit_kernel<<<dim3(Cn / 32, GK / 32), dim3(32, 8)>>>(w_proj, wph, wpl, Cn);
    // 1. qkv = x @ w_attn
    hgemm3_kernel<<<dim3(QKVW / 128, ROWS / 128), 256, GSM>>>(xh, xl, wah, wal, qkvp, QKVW);
    // 2. RoPE + split q,k
    rope_split_kernel<<<(ROWS * 4 * 5 * 64) / 256, 256>>>(cosb, sinb);
    // 3. v split + transpose
    vsplit_kernel<<<dim3(Tn / 32, 4, 8), dim3(32, 8)>>>();
    // 4. attention -> yh/yl
    attn_kernel<<<dim3(Tn / 128, 16, 2), 256, ATT_SMEM>>>();
    // 5. out = y @ w_proj
    hgemm3_kernel<<<dim3(Cn / 128, ROWS / 128), 256, GSM>>>(yh, yl, wph, wpl, out, Cn);
}

// round 5
// speedup vs baseline: 2.4771x; 1.0461x over previous
#include <cuda_runtime.h>
#include <cuda_bf16.h>
#include <cstdint>
#include <cstddef>

// ---------------------------------------------------------------------------
// SelfAttention on sm_103 via baseline-PTX tensor cores (mma.sync bf16 x3).
// R5: term-major MMA ordering (same-acc reuse distance 8 MMAs instead of 1;
// the asm-volatile MMAs cannot be reordered by ptxas, so R4 paid full RAW
// latency on every compensation MMA) + ldmatrix.x4 fragment loads.
// ---------------------------------------------------------------------------

#define Tn     2048
#define Cn     2048
#define QKVW   3072          // (16 + 2*4) * 128
#define ROWS   4096          // B*T
#define GK     2048          // K dim of both big GEMMs

typedef __nv_bfloat16 bf16;

__device__ __align__(16) float g_qkv[(size_t)ROWS * QKVW];
__device__ __align__(16) bf16  g_xh[(size_t)ROWS * GK];
__device__ __align__(16) bf16  g_xl[(size_t)ROWS * GK];
__device__ __align__(16) bf16  g_wah[(size_t)QKVW * GK];
__device__ __align__(16) bf16  g_wal[(size_t)QKVW * GK];
__device__ __align__(16) bf16  g_wph[(size_t)Cn * GK];
__device__ __align__(16) bf16  g_wpl[(size_t)Cn * GK];
__device__ __align__(16) bf16  g_qh[(size_t)2 * 16 * Tn * 128];
__device__ __align__(16) bf16  g_ql[(size_t)2 * 16 * Tn * 128];
__device__ __align__(16) bf16  g_kh[(size_t)2 * 4 * Tn * 128];
__device__ __align__(16) bf16  g_kl[(size_t)2 * 4 * Tn * 128];
__device__ __align__(16) bf16  g_vth[(size_t)2 * 4 * 128 * Tn];
__device__ __align__(16) bf16  g_vtl[(size_t)2 * 4 * 128 * Tn];
__device__ __align__(16) bf16  g_yh[(size_t)ROWS * Cn];
__device__ __align__(16) bf16  g_yl[(size_t)ROWS * Cn];

// 1/sqrt(128) * log2(e): softmax scale + exp->exp2, folded into q
#define QK_SCALE (0.08838834764831845f * 1.4426950408889634f)

// ============================ helpers =======================================
__device__ __forceinline__ float ex2f(float x) {
    float r;
    asm("ex2.approx.ftz.f32 %0, %1;" : "=f"(r) : "f"(x));
    return r;
}
// pack two fp32 -> bf16x2 reg; 'lo' arg goes to bits [15:0]
__device__ __forceinline__ uint32_t pkbf2(float lo, float hi) {
    uint32_t r;
    asm("cvt.rn.bf16x2.f32 %0, %1, %2;" : "=r"(r) : "f"(hi), "f"(lo));
    return r;
}
__device__ __forceinline__ void mma_bf16(float (&d)[4], const uint32_t (&a)[4],
                                         const uint32_t* b) {
    asm volatile(
        "mma.sync.aligned.m16n8k16.row.col.f32.bf16.bf16.f32 "
        "{%0,%1,%2,%3}, {%4,%5,%6,%7}, {%8,%9}, {%0,%1,%2,%3};"
        : "+f"(d[0]), "+f"(d[1]), "+f"(d[2]), "+f"(d[3])
        : "r"(a[0]), "r"(a[1]), "r"(a[2]), "r"(a[3]), "r"(b[0]), "r"(b[1]));
}
__device__ __forceinline__ void ldsm4(uint32_t* r, uint32_t a) {
    asm volatile("ldmatrix.sync.aligned.m8n8.x4.shared.b16 {%0,%1,%2,%3}, [%4];"
                 : "=r"(r[0]), "=r"(r[1]), "=r"(r[2]), "=r"(r[3]) : "r"(a));
}
__device__ __forceinline__ uint32_t smem_u32(const void* p) {
    uint32_t a;
    asm("{ .reg .u64 t; cvta.to.shared.u64 t, %1; cvt.u32.u64 %0, t; }"
        : "=r"(a) : "l"(p));
    return a;
}
#define CP16(dst, src) \
    asm volatile("cp.async.cg.shared.global [%0], [%1], 16;" \
                 :: "r"(dst), "l"(src) : "memory")
#define CPCOMMIT() asm volatile("cp.async.commit_group;" ::: "memory")
#define CPWAIT1()  asm volatile("cp.async.wait_group 1;" ::: "memory")
#define CPWAIT0()  asm volatile("cp.async.wait_group 0;" ::: "memory")

// ---------------------------------------------------------------------------
// split x -> bf16 hi/lo (grid-stride over float4)
// ---------------------------------------------------------------------------
__global__ __launch_bounds__(256) void splitx_kernel(const float* __restrict__ x) {
    size_t i = ((size_t)blockIdx.x * 256 + threadIdx.x) * 4;
    float4 v = *(const float4*)(x + i);
    uint32_t h0 = pkbf2(v.x, v.y), h1 = pkbf2(v.z, v.w);
    float e0 = v.x - __uint_as_float(h0 << 16);
    float e1 = v.y - __uint_as_float(h0 & 0xffff0000u);
    float e2 = v.z - __uint_as_float(h1 << 16);
    float e3 = v.w - __uint_as_float(h1 & 0xffff0000u);
    *(uint2*)(g_xh + i) = make_uint2(h0, h1);
    *(uint2*)(g_xl + i) = make_uint2(pkbf2(e0, e1), pkbf2(e2, e3));
}

// ---------------------------------------------------------------------------
// transpose + split weights: in [2048][Ccols] fp32 -> hi/lo [Ccols][2048] bf16
// ---------------------------------------------------------------------------
__global__ __launch_bounds__(256) void wsplit_kernel(
    const float* __restrict__ in, bf16* __restrict__ hi, bf16* __restrict__ lo,
    int Ccols)
{
    __shared__ float tb[32][33];
    const int bx = blockIdx.x * 32, by = blockIdx.y * 32;
    const int tx = threadIdx.x, ty = threadIdx.y;
#pragma unroll
    for (int j = 0; j < 32; j += 8)
        tb[ty + j][tx] = in[(size_t)(by + ty + j) * Ccols + bx + tx];
    __syncthreads();
#pragma unroll
    for (int j = 0; j < 32; j += 8) {
        float v = tb[tx][ty + j];
        size_t o = (size_t)(bx + ty + j) * GK + by + tx;
        bf16 h = __float2bfloat16(v);
        hi[o] = h;
        lo[o] = __float2bfloat16(v - __bfloat162float(h));
    }
}

// ---------------------------------------------------------------------------
// bf16x3 GEMM: C[M,N] = A[M,2048] @ BT[N,2048]^T.  A,BT given as hi/lo bf16.
// 128x128 CTA tile, kchunk 32, cp.async double buffer, 8 warps (4m x 2n),
// warp tile 32x64, ldmatrix fragments, term-major MMA ordering.
// ---------------------------------------------------------------------------
#define GS_STAGE 40960
#define GSM (2 * GS_STAGE)

__global__ __launch_bounds__(256, 2) void hgemm3_kernel(
    const bf16* __restrict__ Ah, const bf16* __restrict__ Al,
    const bf16* __restrict__ Bh, const bf16* __restrict__ Bl,
    float* __restrict__ C, int N)
{
    extern __shared__ char sm[];
    const uint32_t sb = smem_u32(sm);
    const int tid = threadIdx.x;
    const int lane = tid & 31, wid = tid >> 5;
    const int lg = lane >> 2, tq = lane & 3;
    const int mi = wid & 3, ni = wid >> 2;
    const size_t m0 = (size_t)blockIdx.y * 128, n0 = (size_t)blockIdx.x * 128;

    // ldmatrix per-lane bases (within a stage)
    const uint32_t abase =
        (uint32_t)((mi * 32 + (lane & 15)) * 80 + (lane >> 4) * 16);
    const uint32_t bbase =
        (uint32_t)(20480 + (ni * 64 + (lane & 7) + ((lane >> 4) * 8)) * 80 +
                   ((lane >> 3) & 1) * 16);

    // per-thread global->smem: 2 x 16B per operand per stage (full 64B rows)
    const int lr = tid >> 1, lh = tid & 1;
    const bf16* pAh = Ah + (m0 + lr) * GK + lh * 16;
    const bf16* pAl = Al + (m0 + lr) * GK + lh * 16;
    const bf16* pBh = Bh + (n0 + lr) * GK + lh * 16;
    const bf16* pBl = Bl + (n0 + lr) * GK + lh * 16;
    const uint32_t sdst = sb + lr * 80 + lh * 32;

    float c[2][8][4];
#pragma unroll
    for (int a = 0; a < 2; a++)
#pragma unroll
        for (int b = 0; b < 8; b++)
#pragma unroll
            for (int d = 0; d < 4; d++) c[a][b][d] = 0.f;

    // stage 0
    {
        uint32_t d0 = sdst;
        CP16(d0,              pAh);
        CP16(d0 + 16,         pAh + 8);
        CP16(d0 + 10240,      pAl);
        CP16(d0 + 10240 + 16, pAl + 8);
        CP16(d0 + 20480,      pBh);
        CP16(d0 + 20480 + 16, pBh + 8);
        CP16(d0 + 30720,      pBl);
        CP16(d0 + 30720 + 16, pBl + 8);
        CPCOMMIT();
    }

#pragma unroll 1
    for (int kt = 0; kt < GK / 32; kt++) {
        const int s = kt & 1;
        if (kt + 1 < GK / 32) {
            uint32_t d0 = sdst + (s ^ 1) * GS_STAGE;
            size_t off = (size_t)(kt + 1) * 32;
            CP16(d0,              pAh + off);
            CP16(d0 + 16,         pAh + off + 8);
            CP16(d0 + 10240,      pAl + off);
            CP16(d0 + 10240 + 16, pAl + off + 8);
            CP16(d0 + 20480,      pBh + off);
            CP16(d0 + 20480 + 16, pBh + off + 8);
            CP16(d0 + 30720,      pBl + off);
            CP16(d0 + 30720 + 16, pBl + off + 8);
            CPCOMMIT();
            CPWAIT1();
        } else {
            CPWAIT0();
        }
        __syncthreads();

        const uint32_t stg = sb + s * GS_STAGE;
#pragma unroll
        for (int kk = 0; kk < 2; kk++) {
            // B fragments for all 8 n-frags (hi+lo)
            uint32_t bh[8][2], bl[8][2];
#pragma unroll
            for (int p = 0; p < 4; p++) {
                uint32_t ba = stg + bbase + p * (16 * 80) + kk * 32;
                ldsm4(&bh[2 * p][0], ba);
                ldsm4(&bl[2 * p][0], ba + 10240);
            }
#pragma unroll
            for (int mt = 0; mt < 2; mt++) {
                uint32_t ah[4], al[4];
                uint32_t aa = stg + abase + mt * (16 * 80) + kk * 32;
                ldsm4(ah, aa);
                ldsm4(al, aa + 10240);
#pragma unroll
                for (int nt = 0; nt < 8; nt++) mma_bf16(c[mt][nt], ah, bh[nt]);
#pragma unroll
                for (int nt = 0; nt < 8; nt++) mma_bf16(c[mt][nt], ah, bl[nt]);
#pragma unroll
                for (int nt = 0; nt < 8; nt++) mma_bf16(c[mt][nt], al, bh[nt]);
            }
        }
        __syncthreads();
    }

#pragma unroll
    for (int mt = 0; mt < 2; mt++) {
        size_t r0 = m0 + mi * 32 + mt * 16 + lg;
#pragma unroll
        for (int nt = 0; nt < 8; nt++) {
            size_t col = n0 + ni * 64 + nt * 8 + tq * 2;
            *(float2*)(C + r0 * N + col)       = make_float2(c[mt][nt][0], c[mt][nt][1]);
            *(float2*)(C + (r0 + 8) * N + col) = make_float2(c[mt][nt][2], c[mt][nt][3]);
        }
    }
}

// ---------------------------------------------------------------------------
// RoPE + bf16 split: q (slots 0-3, scaled) -> g_qh/ql [b][h][t][d];
// k (slot 4) -> g_kh/kl [b][g][t][d]
// ---------------------------------------------------------------------------
__global__ __launch_bounds__(256) void rope_split_kernel(
    const float* __restrict__ cosb, const float* __restrict__ sinb)
{
    int idx = blockIdx.x * 256 + threadIdx.x;     // ROWS*4*5*64
    int d = idx & 63;
    int rg = idx >> 6;
    int slot = rg % 5;
    int q5 = rg / 5;
    int grp = q5 & 3;
    int row = q5 >> 2;
    int b = row >> 11, t = row & (Tn - 1);

    const float* p = g_qkv + (size_t)row * QKVW + grp * 768 + slot * 128 + d;
    float x1 = p[0], x2 = p[64];
    float cc = cosb[t * 64 + d], ss = sinb[t * 64 + d];
    float o1 = x1 * cc - x2 * ss;
    float o2 = x1 * ss + x2 * cc;

    bf16 *dh, *dl;
    size_t base;
    if (slot < 4) {
        o1 *= QK_SCALE; o2 *= QK_SCALE;
        int head = grp * 4 + slot;
        base = ((size_t)(b * 16 + head) * Tn + t) * 128 + d;
        dh = g_qh; dl = g_ql;
    } else {
        base = ((size_t)(b * 4 + grp) * Tn + t) * 128 + d;
        dh = g_kh; dl = g_kl;
    }
    bf16 h1 = __float2bfloat16(o1), h2 = __float2bfloat16(o2);
    dh[base]      = h1;
    dh[base + 64] = h2;
    dl[base]      = __float2bfloat16(o1 - __bfloat162float(h1));
    dl[base + 64] = __float2bfloat16(o2 - __bfloat162float(h2));
}

// ---------------------------------------------------------------------------
// v: split + transpose -> g_vth/vtl [b][g][d][t]
// ---------------------------------------------------------------------------
__global__ __launch_bounds__(256) void vsplit_kernel() {
    __shared__ float tb[32][33];
    const int bg = blockIdx.z;
    const int t0 = blockIdx.x * 32, d0 = blockIdx.y * 32;
    const int tx = threadIdx.x, ty = threadIdx.y;
    const int b = bg >> 2, grp = bg & 3;
#pragma unroll
    for (int j = 0; j < 32; j += 8)
        tb[ty + j][tx] = g_qkv[((size_t)b * Tn + t0 + ty + j) * QKVW +
                               grp * 768 + 640 + d0 + tx];
    __syncthreads();
#pragma unroll
    for (int j = 0; j < 32; j += 8) {
        float v = tb[tx][ty + j];
        size_t o = ((size_t)bg * 128 + d0 + ty + j) * Tn + t0 + tx;
        bf16 h = __float2bfloat16(v);
        g_vth[o] = h;
        g_vtl[o] = __float2bfloat16(v - __bfloat162float(h));
    }
}

// ---------------------------------------------------------------------------
// Flash attention on mma.sync bf16x3, ldmatrix + term-major ordering.
// CTA = (qb, h, b): 128 q rows, 8 warps x m16. Key tiles of 64.
// smem: Qh/Ql [128 rows x 272B], Kh/Kl [64 x 272B], Vth/Vtl [128 d x 144B].
// ---------------------------------------------------------------------------
#define AQ_H 0
#define AQ_L 34816
#define AK_H 69632
#define AK_L 87040
#define AV_H 104448
#define AV_L 122880
#define ATT_SMEM 141312

__global__ __launch_bounds__(256, 1) void attn_kernel() {
    extern __shared__ char sm[];
    const uint32_t sb = smem_u32(sm);
    const int tid = threadIdx.x;
    const int lane = tid & 31, wid = tid >> 5;
    const int lg = lane >> 2, tq = lane & 3;
    const int qb = blockIdx.x, h = blockIdx.y, b = blockIdx.z;
    const int grp = h >> 2;

    // ldmatrix per-lane bases
    const uint32_t qbase = sb + AQ_H + (wid * 16 + (lane & 15)) * 272 +
                           (lane >> 4) * 16;
    const uint32_t kbase = sb + AK_H + ((lane & 7) + ((lane >> 4) * 8)) * 272 +
                           ((lane >> 3) & 1) * 16;
    const uint32_t vbase = sb + AV_H + ((lane & 7) + ((lane >> 4) * 8)) * 144 +
                           ((lane >> 3) & 1) * 16;

    // load Q (hi/lo), 128 x 128 bf16 each
    {
        const bf16* qhp = g_qh + ((size_t)(b * 16 + h) * Tn + qb * 128) * 128;
        const bf16* qlp = g_ql + ((size_t)(b * 16 + h) * Tn + qb * 128) * 128;
#pragma unroll
        for (int it = 0; it < 8; it++) {
            int idx = it * 256 + tid;
            int r = idx >> 4, hx = idx & 15;
            *(uint4*)(sm + AQ_H + r * 272 + hx * 16) = *(const uint4*)(qhp + (size_t)r * 128 + hx * 8);
            *(uint4*)(sm + AQ_L + r * 272 + hx * 16) = *(const uint4*)(qlp + (size_t)r * 128 + hx * 8);
        }
    }

    float o[16][4];
#pragma unroll
    for (int i = 0; i < 16; i++)
#pragma unroll
        for (int j = 0; j < 4; j++) o[i][j] = 0.f;
    float m0 = __int_as_float(0xff800000), m1 = m0;
    float l0 = 0.f, l1 = 0.f;

    const bf16* khp = g_kh + (size_t)(b * 4 + grp) * Tn * 128;
    const bf16* klp = g_kl + (size_t)(b * 4 + grp) * Tn * 128;
    const bf16* vhp = g_vth + (size_t)(b * 4 + grp) * 128 * Tn;
    const bf16* vlp = g_vtl + (size_t)(b * 4 + grp) * 128 * Tn;

#pragma unroll 1
    for (int kt = 0; kt < Tn / 64; kt++) {
        __syncthreads();   // prev tile's reads done (also orders Q on kt=0)
#pragma unroll
        for (int it = 0; it < 4; it++) {
            int idx = it * 256 + tid;
            int r = idx >> 4, hx = idx & 15;
            size_t go = ((size_t)kt * 64 + r) * 128 + hx * 8;
            *(uint4*)(sm + AK_H + r * 272 + hx * 16) = *(const uint4*)(khp + go);
            *(uint4*)(sm + AK_L + r * 272 + hx * 16) = *(const uint4*)(klp + go);
        }
#pragma unroll
        for (int it = 0; it < 4; it++) {
            int idx = it * 256 + tid;
            int r = idx >> 3, hx = idx & 7;
            size_t go = (size_t)r * Tn + kt * 64 + hx * 8;
            *(uint4*)(sm + AV_H + r * 144 + hx * 16) = *(const uint4*)(vhp + go);
            *(uint4*)(sm + AV_L + r * 144 + hx * 16) = *(const uint4*)(vlp + go);
        }
        __syncthreads();

        // ---- S = Q K^T (bf16x3), warp strip m16 x n64 ----
        float s[8][4];
#pragma unroll
        for (int i = 0; i < 8; i++)
#pragma unroll
            for (int j = 0; j < 4; j++) s[i][j] = 0.f;

#pragma unroll
        for (int kk = 0; kk < 8; kk++) {
            uint32_t qah[4], qal[4];
            ldsm4(qah, qbase + kk * 32);
            ldsm4(qal, qbase + (AQ_L - AQ_H) + kk * 32);
            uint32_t kbh[8][2], kbl[8][2];
#pragma unroll
            for (int p = 0; p < 4; p++) {
                uint32_t ka = kbase + p * (16 * 272) + kk * 32;
                ldsm4(&kbh[2 * p][0], ka);
                ldsm4(&kbl[2 * p][0], ka + (AK_L - AK_H));
            }
#pragma unroll
            for (int nt = 0; nt < 8; nt++) mma_bf16(s[nt], qah, kbh[nt]);
#pragma unroll
            for (int nt = 0; nt < 8; nt++) mma_bf16(s[nt], qah, kbl[nt]);
#pragma unroll
            for (int nt = 0; nt < 8; nt++) mma_bf16(s[nt], qal, kbh[nt]);
        }

        // ---- online softmax (2 rows per lane: lg, lg+8) ----
        float mx0 = s[0][0], mx1 = s[0][2];
#pragma unroll
        for (int nt = 0; nt < 8; nt++) {
            mx0 = fmaxf(mx0, fmaxf(s[nt][0], s[nt][1]));
            mx1 = fmaxf(mx1, fmaxf(s[nt][2], s[nt][3]));
        }
        mx0 = fmaxf(mx0, __shfl_xor_sync(0xffffffffu, mx0, 1));
        mx0 = fmaxf(mx0, __shfl_xor_sync(0xffffffffu, mx0, 2));
        mx1 = fmaxf(mx1, __shfl_xor_sync(0xffffffffu, mx1, 1));
        mx1 = fmaxf(mx1, __shfl_xor_sync(0xffffffffu, mx1, 2));
        float mn0 = fmaxf(m0, mx0), mn1 = fmaxf(m1, mx1);
        float cr0 = ex2f(m0 - mn0), cr1 = ex2f(m1 - mn1);
        m0 = mn0; m1 = mn1;
        float sum0 = 0.f, sum1 = 0.f;
#pragma unroll
        for (int nt = 0; nt < 8; nt++) {
            s[nt][0] = ex2f(s[nt][0] - mn0);
            s[nt][1] = ex2f(s[nt][1] - mn0);
            s[nt][2] = ex2f(s[nt][2] - mn1);
            s[nt][3] = ex2f(s[nt][3] - mn1);
            sum0 += s[nt][0] + s[nt][1];
            sum1 += s[nt][2] + s[nt][3];
        }
        sum0 += __shfl_xor_sync(0xffffffffu, sum0, 1);
        sum0 += __shfl_xor_sync(0xffffffffu, sum0, 2);
        sum1 += __shfl_xor_sync(0xffffffffu, sum1, 1);
        sum1 += __shfl_xor_sync(0xffffffffu, sum1, 2);
        l0 = l0 * cr0 + sum0;
        l1 = l1 * cr1 + sum1;
#pragma unroll
        for (int nt = 0; nt < 16; nt++) {
            o[nt][0] *= cr0; o[nt][1] *= cr0;
            o[nt][2] *= cr1; o[nt][3] *= cr1;
        }

        // ---- O += P V (bf16x3); P frags straight from S accum regs ----
#pragma unroll
        for (int kk = 0; kk < 4; kk++) {
            uint32_t ph[4], pl[4];
            {
                float e0 = s[2 * kk][0], e1 = s[2 * kk][1];
                ph[0] = pkbf2(e0, e1);
                pl[0] = pkbf2(e0 - __uint_as_float(ph[0] << 16),
                              e1 - __uint_as_float(ph[0] & 0xffff0000u));
                e0 = s[2 * kk][2]; e1 = s[2 * kk][3];
                ph[1] = pkbf2(e0, e1);
                pl[1] = pkbf2(e0 - __uint_as_float(ph[1] << 16),
                              e1 - __uint_as_float(ph[1] & 0xffff0000u));
                e0 = s[2 * kk + 1][0]; e1 = s[2 * kk + 1][1];
                ph[2] = pkbf2(e0, e1);
                pl[2] = pkbf2(e0 - __uint_as_float(ph[2] << 16),
                              e1 - __uint_as_float(ph[2] & 0xffff0000u));
                e0 = s[2 * kk + 1][2]; e1 = s[2 * kk + 1][3];
                ph[3] = pkbf2(e0, e1);
                pl[3] = pkbf2(e0 - __uint_as_float(ph[3] << 16),
                              e1 - __uint_as_float(ph[3] & 0xffff0000u));
            }
#pragma unroll
            for (int blk = 0; blk < 2; blk++) {
                uint32_t vbh[8][2], vbl[8][2];
#pragma unroll
                for (int p = 0; p < 4; p++) {
                    uint32_t va = vbase + (blk * 64 + p * 16) * 144 + kk * 32;
                    ldsm4(&vbh[2 * p][0], va);
                    ldsm4(&vbl[2 * p][0], va + (AV_L - AV_H));
                }
#pragma unroll
                for (int j = 0; j < 8; j++) mma_bf16(o[blk * 8 + j], ph, vbh[j]);
#pragma unroll
                for (int j = 0; j < 8; j++) mma_bf16(o[blk * 8 + j], ph, vbl[j]);
#pragma unroll
                for (int j = 0; j < 8; j++) mma_bf16(o[blk * 8 + j], pl, vbh[j]);
            }
        }
    }

    // ---- epilogue: y = O / l, split to bf16 hi/lo ----
    float i0 = 1.f / l0, i1 = 1.f / l1;
    size_t row0 = (size_t)b * Tn + qb * 128 + wid * 16 + lg;
#pragma unroll
    for (int nt = 0; nt < 16; nt++) {
        int col = h * 128 + nt * 8 + tq * 2;
        float v0 = o[nt][0] * i0, v1 = o[nt][1] * i0;
        uint32_t hh = pkbf2(v0, v1);
        uint32_t ll = pkbf2(v0 - __uint_as_float(hh << 16),
                            v1 - __uint_as_float(hh & 0xffff0000u));
        *(uint32_t*)(g_yh + row0 * Cn + col) = hh;
        *(uint32_t*)(g_yl + row0 * Cn + col) = ll;
        v0 = o[nt][2] * i1; v1 = o[nt][3] * i1;
        hh = pkbf2(v0, v1);
        ll = pkbf2(v0 - __uint_as_float(hh << 16),
                   v1 - __uint_as_float(hh & 0xffff0000u));
        *(uint32_t*)(g_yh + (row0 + 8) * Cn + col) = hh;
        *(uint32_t*)(g_yl + (row0 + 8) * Cn + col) = ll;
    }
}

// ---------------------------------------------------------------------------
extern "C" void kernel_launch(void* const* d_in, const int* in_sizes, int n_in,
                              void* d_out, int out_size) {
    const float* x      = (const float*)d_in[0];
    const float* cosb   = (const float*)d_in[1];
    const float* sinb   = (const float*)d_in[2];
    const float* w_attn = (const float*)d_in[3];
    const float* w_proj = (const float*)d_in[4];
    float* out = (float*)d_out;
    (void)in_sizes; (void)n_in; (void)out_size;

    (void)cudaFuncSetAttribute(hgemm3_kernel,
                               cudaFuncAttributeMaxDynamicSharedMemorySize, GSM);
    (void)cudaFuncSetAttribute(attn_kernel,
                               cudaFuncAttributeMaxDynamicSharedMemorySize, ATT_SMEM);

    float* qkvp = nullptr;
    bf16 *xh, *xl, *wah, *wal, *wph, *wpl, *yh, *yl;
    (void)cudaGetSymbolAddress((void**)&qkvp, g_qkv);
    (void)cudaGetSymbolAddress((void**)&xh, g_xh);
    (void)cudaGetSymbolAddress((void**)&xl, g_xl);
    (void)cudaGetSymbolAddress((void**)&wah, g_wah);
    (void)cudaGetSymbolAddress((void**)&wal, g_wal);
    (void)cudaGetSymbolAddress((void**)&wph, g_wph);
    (void)cudaGetSymbolAddress((void**)&wpl, g_wpl);
    (void)cudaGetSymbolAddress((void**)&yh, g_yh);
    (void)cudaGetSymbolAddress((void**)&yl, g_yl);

    // 0. splits
    splitx_kernel<<<(ROWS * GK / 4) / 256, 256>>>(x);
    wsplit_kernel<<<dim3(QKVW / 32, GK / 32), dim3(32, 8)>>>(w_attn, wah, wal, QKVW);
    wsplit_kernel<<<dim3(Cn / 32, GK / 32), dim3(32, 8)>>>(w_proj, wph, wpl, Cn);
    // 1. qkv = x @ w_attn
    hgemm3_kernel<<<dim3(QKVW / 128, ROWS / 128), 256, GSM>>>(xh, xl, wah, wal, qkvp, QKVW);
    // 2. RoPE + split q,k
    rope_split_kernel<<<(ROWS * 4 * 5 * 64) / 256, 256>>>(cosb, sinb);
    // 3. v split + transpose
    vsplit_kernel<<<dim3(Tn / 32, 4, 8), dim3(32, 8)>>>();
    // 4. attention -> yh/yl
    attn_kernel<<<dim3(Tn / 128, 16, 2), 256, ATT_SMEM>>>();
    // 5. out = y @ w_proj
    hgemm3_kernel<<<dim3(Cn / 128, ROWS / 128), 256, GSM>>>(yh, yl, wph, wpl, out, Cn);
}

// round 6
// speedup vs baseline: 2.5003x; 1.0094x over previous
#include <cuda_runtime.h>
#include <cuda_bf16.h>
#include <cstdint>
#include <cstddef>

// ---------------------------------------------------------------------------
// SelfAttention on sm_103 via baseline-PTX tensor cores (mma.sync bf16 x3).
// R6: register-pressure fix. launch_bounds(256,2) caps regs at 128; R5 kept
// ~185 live (64 acc + 32 B-frags + 16 A-frags + addr) -> mainloop spills.
// Now a single 16-reg B buffer is loaded with B_hi, used for terms ah*bh and
// al*bh, then RELOADED with B_lo for term ah*bl. Peak live ~116. Same
// restructure in attention S / PV loops.
// ---------------------------------------------------------------------------

#define Tn     2048
#define Cn     2048
#define QKVW   3072          // (16 + 2*4) * 128
#define ROWS   4096          // B*T
#define GK     2048          // K dim of both big GEMMs

typedef __nv_bfloat16 bf16;

__device__ __align__(16) float g_qkv[(size_t)ROWS * QKVW];
__device__ __align__(16) bf16  g_xh[(size_t)ROWS * GK];
__device__ __align__(16) bf16  g_xl[(size_t)ROWS * GK];
__device__ __align__(16) bf16  g_wah[(size_t)QKVW * GK];
__device__ __align__(16) bf16  g_wal[(size_t)QKVW * GK];
__device__ __align__(16) bf16  g_wph[(size_t)Cn * GK];
__device__ __align__(16) bf16  g_wpl[(size_t)Cn * GK];
__device__ __align__(16) bf16  g_qh[(size_t)2 * 16 * Tn * 128];
__device__ __align__(16) bf16  g_ql[(size_t)2 * 16 * Tn * 128];
__device__ __align__(16) bf16  g_kh[(size_t)2 * 4 * Tn * 128];
__device__ __align__(16) bf16  g_kl[(size_t)2 * 4 * Tn * 128];
__device__ __align__(16) bf16  g_vth[(size_t)2 * 4 * 128 * Tn];
__device__ __align__(16) bf16  g_vtl[(size_t)2 * 4 * 128 * Tn];
__device__ __align__(16) bf16  g_yh[(size_t)ROWS * Cn];
__device__ __align__(16) bf16  g_yl[(size_t)ROWS * Cn];

// 1/sqrt(128) * log2(e): softmax scale + exp->exp2, folded into q
#define QK_SCALE (0.08838834764831845f * 1.4426950408889634f)

// ============================ helpers =======================================
__device__ __forceinline__ float ex2f(float x) {
    float r;
    asm("ex2.approx.ftz.f32 %0, %1;" : "=f"(r) : "f"(x));
    return r;
}
// pack two fp32 -> bf16x2 reg; 'lo' arg goes to bits [15:0]
__device__ __forceinline__ uint32_t pkbf2(float lo, float hi) {
    uint32_t r;
    asm("cvt.rn.bf16x2.f32 %0, %1, %2;" : "=r"(r) : "f"(hi), "f"(lo));
    return r;
}
__device__ __forceinline__ void mma_bf16(float (&d)[4], const uint32_t (&a)[4],
                                         const uint32_t* b) {
    asm volatile(
        "mma.sync.aligned.m16n8k16.row.col.f32.bf16.bf16.f32 "
        "{%0,%1,%2,%3}, {%4,%5,%6,%7}, {%8,%9}, {%0,%1,%2,%3};"
        : "+f"(d[0]), "+f"(d[1]), "+f"(d[2]), "+f"(d[3])
        : "r"(a[0]), "r"(a[1]), "r"(a[2]), "r"(a[3]), "r"(b[0]), "r"(b[1]));
}
__device__ __forceinline__ void ldsm4(uint32_t* r, uint32_t a) {
    asm volatile("ldmatrix.sync.aligned.m8n8.x4.shared.b16 {%0,%1,%2,%3}, [%4];"
                 : "=r"(r[0]), "=r"(r[1]), "=r"(r[2]), "=r"(r[3]) : "r"(a));
}
__device__ __forceinline__ uint32_t smem_u32(const void* p) {
    uint32_t a;
    asm("{ .reg .u64 t; cvta.to.shared.u64 t, %1; cvt.u32.u64 %0, t; }"
        : "=r"(a) : "l"(p));
    return a;
}
#define CP16(dst, src) \
    asm volatile("cp.async.cg.shared.global [%0], [%1], 16;" \
                 :: "r"(dst), "l"(src) : "memory")
#define CPCOMMIT() asm volatile("cp.async.commit_group;" ::: "memory")
#define CPWAIT1()  asm volatile("cp.async.wait_group 1;" ::: "memory")
#define CPWAIT0()  asm volatile("cp.async.wait_group 0;" ::: "memory")

// ---------------------------------------------------------------------------
// split x -> bf16 hi/lo (grid-stride over float4)
// ---------------------------------------------------------------------------
__global__ __launch_bounds__(256) void splitx_kernel(const float* __restrict__ x) {
    size_t i = ((size_t)blockIdx.x * 256 + threadIdx.x) * 4;
    float4 v = *(const float4*)(x + i);
    uint32_t h0 = pkbf2(v.x, v.y), h1 = pkbf2(v.z, v.w);
    float e0 = v.x - __uint_as_float(h0 << 16);
    float e1 = v.y - __uint_as_float(h0 & 0xffff0000u);
    float e2 = v.z - __uint_as_float(h1 << 16);
    float e3 = v.w - __uint_as_float(h1 & 0xffff0000u);
    *(uint2*)(g_xh + i) = make_uint2(h0, h1);
    *(uint2*)(g_xl + i) = make_uint2(pkbf2(e0, e1), pkbf2(e2, e3));
}

// ---------------------------------------------------------------------------
// transpose + split weights: in [2048][Ccols] fp32 -> hi/lo [Ccols][2048] bf16
// ---------------------------------------------------------------------------
__global__ __launch_bounds__(256) void wsplit_kernel(
    const float* __restrict__ in, bf16* __restrict__ hi, bf16* __restrict__ lo,
    int Ccols)
{
    __shared__ float tb[32][33];
    const int bx = blockIdx.x * 32, by = blockIdx.y * 32;
    const int tx = threadIdx.x, ty = threadIdx.y;
#pragma unroll
    for (int j = 0; j < 32; j += 8)
        tb[ty + j][tx] = in[(size_t)(by + ty + j) * Ccols + bx + tx];
    __syncthreads();
#pragma unroll
    for (int j = 0; j < 32; j += 8) {
        float v = tb[tx][ty + j];
        size_t o = (size_t)(bx + ty + j) * GK + by + tx;
        bf16 h = __float2bfloat16(v);
        hi[o] = h;
        lo[o] = __float2bfloat16(v - __bfloat162float(h));
    }
}

// ---------------------------------------------------------------------------
// bf16x3 GEMM: C[M,N] = A[M,2048] @ BT[N,2048]^T.  A,BT given as hi/lo bf16.
// 128x128 CTA tile, kchunk 32, cp.async double buffer, 8 warps (4m x 2n),
// warp tile 32x64, ldmatrix fragments, B-buffer-reuse term ordering.
// ---------------------------------------------------------------------------
#define GS_STAGE 40960
#define GSM (2 * GS_STAGE)

__global__ __launch_bounds__(256, 2) void hgemm3_kernel(
    const bf16* __restrict__ Ah, const bf16* __restrict__ Al,
    const bf16* __restrict__ Bh, const bf16* __restrict__ Bl,
    float* __restrict__ C, int N)
{
    extern __shared__ char sm[];
    const uint32_t sb = smem_u32(sm);
    const int tid = threadIdx.x;
    const int lane = tid & 31, wid = tid >> 5;
    const int lg = lane >> 2, tq = lane & 3;
    const int mi = wid & 3, ni = wid >> 2;
    const size_t m0 = (size_t)blockIdx.y * 128, n0 = (size_t)blockIdx.x * 128;

    // ldmatrix per-lane bases (within a stage)
    const uint32_t abase =
        (uint32_t)((mi * 32 + (lane & 15)) * 80 + (lane >> 4) * 16);
    const uint32_t bbase =
        (uint32_t)(20480 + (ni * 64 + (lane & 7) + ((lane >> 4) * 8)) * 80 +
                   ((lane >> 3) & 1) * 16);

    // per-thread global->smem: 2 x 16B per operand per stage (full 64B rows)
    const int lr = tid >> 1, lh = tid & 1;
    const bf16* pAh = Ah + (m0 + lr) * GK + lh * 16;
    const bf16* pAl = Al + (m0 + lr) * GK + lh * 16;
    const bf16* pBh = Bh + (n0 + lr) * GK + lh * 16;
    const bf16* pBl = Bl + (n0 + lr) * GK + lh * 16;
    const uint32_t sdst = sb + lr * 80 + lh * 32;

    float c[2][8][4];
#pragma unroll
    for (int a = 0; a < 2; a++)
#pragma unroll
        for (int b = 0; b < 8; b++)
#pragma unroll
            for (int d = 0; d < 4; d++) c[a][b][d] = 0.f;

    // stage 0
    {
        uint32_t d0 = sdst;
        CP16(d0,              pAh);
        CP16(d0 + 16,         pAh + 8);
        CP16(d0 + 10240,      pAl);
        CP16(d0 + 10240 + 16, pAl + 8);
        CP16(d0 + 20480,      pBh);
        CP16(d0 + 20480 + 16, pBh + 8);
        CP16(d0 + 30720,      pBl);
        CP16(d0 + 30720 + 16, pBl + 8);
        CPCOMMIT();
    }

#pragma unroll 1
    for (int kt = 0; kt < GK / 32; kt++) {
        const int s = kt & 1;
        if (kt + 1 < GK / 32) {
            uint32_t d0 = sdst + (s ^ 1) * GS_STAGE;
            size_t off = (size_t)(kt + 1) * 32;
            CP16(d0,              pAh + off);
            CP16(d0 + 16,         pAh + off + 8);
            CP16(d0 + 10240,      pAl + off);
            CP16(d0 + 10240 + 16, pAl + off + 8);
            CP16(d0 + 20480,      pBh + off);
            CP16(d0 + 20480 + 16, pBh + off + 8);
            CP16(d0 + 30720,      pBl + off);
            CP16(d0 + 30720 + 16, pBl + off + 8);
            CPCOMMIT();
            CPWAIT1();
        } else {
            CPWAIT0();
        }
        __syncthreads();

        const uint32_t stg = sb + s * GS_STAGE;
#pragma unroll
        for (int kk = 0; kk < 2; kk++) {
            // A fragments (hi + lo), 16 regs
            uint32_t ah[2][4], al[2][4];
#pragma unroll
            for (int mt = 0; mt < 2; mt++) {
                uint32_t aa = stg + abase + mt * (16 * 80) + kk * 32;
                ldsm4(ah[mt], aa);
                ldsm4(al[mt], aa + 10240);
            }
            // single B buffer, 16 regs: first B_hi
            uint32_t bb[8][2];
#pragma unroll
            for (int p = 0; p < 4; p++)
                ldsm4(&bb[2 * p][0], stg + bbase + p * (16 * 80) + kk * 32);
            // term 1: ah * bh ; term 3: al * bh
#pragma unroll
            for (int mt = 0; mt < 2; mt++)
#pragma unroll
                for (int nt = 0; nt < 8; nt++) mma_bf16(c[mt][nt], ah[mt], bb[nt]);
#pragma unroll
            for (int mt = 0; mt < 2; mt++)
#pragma unroll
                for (int nt = 0; nt < 8; nt++) mma_bf16(c[mt][nt], al[mt], bb[nt]);
            // reload buffer with B_lo
#pragma unroll
            for (int p = 0; p < 4; p++)
                ldsm4(&bb[2 * p][0], stg + bbase + 10240 + p * (16 * 80) + kk * 32);
            // term 2: ah * bl
#pragma unroll
            for (int mt = 0; mt < 2; mt++)
#pragma unroll
                for (int nt = 0; nt < 8; nt++) mma_bf16(c[mt][nt], ah[mt], bb[nt]);
        }
        __syncthreads();
    }

#pragma unroll
    for (int mt = 0; mt < 2; mt++) {
        size_t r0 = m0 + mi * 32 + mt * 16 + lg;
#pragma unroll
        for (int nt = 0; nt < 8; nt++) {
            size_t col = n0 + ni * 64 + nt * 8 + tq * 2;
            *(float2*)(C + r0 * N + col)       = make_float2(c[mt][nt][0], c[mt][nt][1]);
            *(float2*)(C + (r0 + 8) * N + col) = make_float2(c[mt][nt][2], c[mt][nt][3]);
        }
    }
}

// ---------------------------------------------------------------------------
// RoPE + bf16 split: q (slots 0-3, scaled) -> g_qh/ql [b][h][t][d];
// k (slot 4) -> g_kh/kl [b][g][t][d]
// ---------------------------------------------------------------------------
__global__ __launch_bounds__(256) void rope_split_kernel(
    const float* __restrict__ cosb, const float* __restrict__ sinb)
{
    int idx = blockIdx.x * 256 + threadIdx.x;     // ROWS*4*5*64
    int d = idx & 63;
    int rg = idx >> 6;
    int slot = rg % 5;
    int q5 = rg / 5;
    int grp = q5 & 3;
    int row = q5 >> 2;
    int b = row >> 11, t = row & (Tn - 1);

    const float* p = g_qkv + (size_t)row * QKVW + grp * 768 + slot * 128 + d;
    float x1 = p[0], x2 = p[64];
    float cc = cosb[t * 64 + d], ss = sinb[t * 64 + d];
    float o1 = x1 * cc - x2 * ss;
    float o2 = x1 * ss + x2 * cc;

    bf16 *dh, *dl;
    size_t base;
    if (slot < 4) {
        o1 *= QK_SCALE; o2 *= QK_SCALE;
        int head = grp * 4 + slot;
        base = ((size_t)(b * 16 + head) * Tn + t) * 128 + d;
        dh = g_qh; dl = g_ql;
    } else {
        base = ((size_t)(b * 4 + grp) * Tn + t) * 128 + d;
        dh = g_kh; dl = g_kl;
    }
    bf16 h1 = __float2bfloat16(o1), h2 = __float2bfloat16(o2);
    dh[base]      = h1;
    dh[base + 64] = h2;
    dl[base]      = __float2bfloat16(o1 - __bfloat162float(h1));
    dl[base + 64] = __float2bfloat16(o2 - __bfloat162float(h2));
}

// ---------------------------------------------------------------------------
// v: split + transpose -> g_vth/vtl [b][g][d][t]
// ---------------------------------------------------------------------------
__global__ __launch_bounds__(256) void vsplit_kernel() {
    __shared__ float tb[32][33];
    const int bg = blockIdx.z;
    const int t0 = blockIdx.x * 32, d0 = blockIdx.y * 32;
    const int tx = threadIdx.x, ty = threadIdx.y;
    const int b = bg >> 2, grp = bg & 3;
#pragma unroll
    for (int j = 0; j < 32; j += 8)
        tb[ty + j][tx] = g_qkv[((size_t)b * Tn + t0 + ty + j) * QKVW +
                               grp * 768 + 640 + d0 + tx];
    __syncthreads();
#pragma unroll
    for (int j = 0; j < 32; j += 8) {
        float v = tb[tx][ty + j];
        size_t o = ((size_t)bg * 128 + d0 + ty + j) * Tn + t0 + tx;
        bf16 h = __float2bfloat16(v);
        g_vth[o] = h;
        g_vtl[o] = __float2bfloat16(v - __bfloat162float(h));
    }
}

// ---------------------------------------------------------------------------
// Flash attention on mma.sync bf16x3, ldmatrix + buffer-reuse term ordering.
// CTA = (qb, h, b): 128 q rows, 8 warps x m16. Key tiles of 64.
// smem: Qh/Ql [128 rows x 272B], Kh/Kl [64 x 272B], Vth/Vtl [128 d x 144B].
// ---------------------------------------------------------------------------
#define AQ_H 0
#define AQ_L 34816
#define AK_H 69632
#define AK_L 87040
#define AV_H 104448
#define AV_L 122880
#define ATT_SMEM 141312

__global__ __launch_bounds__(256, 1) void attn_kernel() {
    extern __shared__ char sm[];
    const uint32_t sb = smem_u32(sm);
    const int tid = threadIdx.x;
    const int lane = tid & 31, wid = tid >> 5;
    const int lg = lane >> 2, tq = lane & 3;
    const int qb = blockIdx.x, h = blockIdx.y, b = blockIdx.z;
    const int grp = h >> 2;

    // ldmatrix per-lane bases
    const uint32_t qbase = sb + AQ_H + (wid * 16 + (lane & 15)) * 272 +
                           (lane >> 4) * 16;
    const uint32_t kbase = sb + AK_H + ((lane & 7) + ((lane >> 4) * 8)) * 272 +
                           ((lane >> 3) & 1) * 16;
    const uint32_t vbase = sb + AV_H + ((lane & 7) + ((lane >> 4) * 8)) * 144 +
                           ((lane >> 3) & 1) * 16;

    // load Q (hi/lo), 128 x 128 bf16 each
    {
        const bf16* qhp = g_qh + ((size_t)(b * 16 + h) * Tn + qb * 128) * 128;
        const bf16* qlp = g_ql + ((size_t)(b * 16 + h) * Tn + qb * 128) * 128;
#pragma unroll
        for (int it = 0; it < 8; it++) {
            int idx = it * 256 + tid;
            int r = idx >> 4, hx = idx & 15;
            *(uint4*)(sm + AQ_H + r * 272 + hx * 16) = *(const uint4*)(qhp + (size_t)r * 128 + hx * 8);
            *(uint4*)(sm + AQ_L + r * 272 + hx * 16) = *(const uint4*)(qlp + (size_t)r * 128 + hx * 8);
        }
    }

    float o[16][4];
#pragma unroll
    for (int i = 0; i < 16; i++)
#pragma unroll
        for (int j = 0; j < 4; j++) o[i][j] = 0.f;
    float m0 = __int_as_float(0xff800000), m1 = m0;
    float l0 = 0.f, l1 = 0.f;

    const bf16* khp = g_kh + (size_t)(b * 4 + grp) * Tn * 128;
    const bf16* klp = g_kl + (size_t)(b * 4 + grp) * Tn * 128;
    const bf16* vhp = g_vth + (size_t)(b * 4 + grp) * 128 * Tn;
    const bf16* vlp = g_vtl + (size_t)(b * 4 + grp) * 128 * Tn;

#pragma unroll 1
    for (int kt = 0; kt < Tn / 64; kt++) {
        __syncthreads();   // prev tile's reads done (also orders Q on kt=0)
#pragma unroll
        for (int it = 0; it < 4; it++) {
            int idx = it * 256 + tid;
            int r = idx >> 4, hx = idx & 15;
            size_t go = ((size_t)kt * 64 + r) * 128 + hx * 8;
            *(uint4*)(sm + AK_H + r * 272 + hx * 16) = *(const uint4*)(khp + go);
            *(uint4*)(sm + AK_L + r * 272 + hx * 16) = *(const uint4*)(klp + go);
        }
#pragma unroll
        for (int it = 0; it < 4; it++) {
            int idx = it * 256 + tid;
            int r = idx >> 3, hx = idx & 7;
            size_t go = (size_t)r * Tn + kt * 64 + hx * 8;
            *(uint4*)(sm + AV_H + r * 144 + hx * 16) = *(const uint4*)(vhp + go);
            *(uint4*)(sm + AV_L + r * 144 + hx * 16) = *(const uint4*)(vlp + go);
        }
        __syncthreads();

        // ---- S = Q K^T (bf16x3), warp strip m16 x n64 ----
        float s[8][4];
#pragma unroll
        for (int i = 0; i < 8; i++)
#pragma unroll
            for (int j = 0; j < 4; j++) s[i][j] = 0.f;

#pragma unroll
        for (int kk = 0; kk < 8; kk++) {
            uint32_t qah[4], qal[4];
            ldsm4(qah, qbase + kk * 32);
            ldsm4(qal, qbase + (AQ_L - AQ_H) + kk * 32);
            uint32_t kb[8][2];
#pragma unroll
            for (int p = 0; p < 4; p++)
                ldsm4(&kb[2 * p][0], kbase + p * (16 * 272) + kk * 32);
            // terms qah*kh, qal*kh
#pragma unroll
            for (int nt = 0; nt < 8; nt++) mma_bf16(s[nt], qah, kb[nt]);
#pragma unroll
            for (int nt = 0; nt < 8; nt++) mma_bf16(s[nt], qal, kb[nt]);
            // reload buffer with K_lo, term qah*kl
#pragma unroll
            for (int p = 0; p < 4; p++)
                ldsm4(&kb[2 * p][0], kbase + (AK_L - AK_H) + p * (16 * 272) + kk * 32);
#pragma unroll
            for (int nt = 0; nt < 8; nt++) mma_bf16(s[nt], qah, kb[nt]);
        }

        // ---- online softmax (2 rows per lane: lg, lg+8) ----
        float mx0 = s[0][0], mx1 = s[0][2];
#pragma unroll
        for (int nt = 0; nt < 8; nt++) {
            mx0 = fmaxf(mx0, fmaxf(s[nt][0], s[nt][1]));
            mx1 = fmaxf(mx1, fmaxf(s[nt][2], s[nt][3]));
        }
        mx0 = fmaxf(mx0, __shfl_xor_sync(0xffffffffu, mx0, 1));
        mx0 = fmaxf(mx0, __shfl_xor_sync(0xffffffffu, mx0, 2));
        mx1 = fmaxf(mx1, __shfl_xor_sync(0xffffffffu, mx1, 1));
        mx1 = fmaxf(mx1, __shfl_xor_sync(0xffffffffu, mx1, 2));
        float mn0 = fmaxf(m0, mx0), mn1 = fmaxf(m1, mx1);
        float cr0 = ex2f(m0 - mn0), cr1 = ex2f(m1 - mn1);
        m0 = mn0; m1 = mn1;
        float sum0 = 0.f, sum1 = 0.f;
#pragma unroll
        for (int nt = 0; nt < 8; nt++) {
            s[nt][0] = ex2f(s[nt][0] - mn0);
            s[nt][1] = ex2f(s[nt][1] - mn0);
            s[nt][2] = ex2f(s[nt][2] - mn1);
            s[nt][3] = ex2f(s[nt][3] - mn1);
            sum0 += s[nt][0] + s[nt][1];
            sum1 += s[nt][2] + s[nt][3];
        }
        sum0 += __shfl_xor_sync(0xffffffffu, sum0, 1);
        sum0 += __shfl_xor_sync(0xffffffffu, sum0, 2);
        sum1 += __shfl_xor_sync(0xffffffffu, sum1, 1);
        sum1 += __shfl_xor_sync(0xffffffffu, sum1, 2);
        l0 = l0 * cr0 + sum0;
        l1 = l1 * cr1 + sum1;
#pragma unroll
        for (int nt = 0; nt < 16; nt++) {
            o[nt][0] *= cr0; o[nt][1] *= cr0;
            o[nt][2] *= cr1; o[nt][3] *= cr1;
        }

        // ---- O += P V (bf16x3); P frags straight from S accum regs ----
#pragma unroll
        for (int kk = 0; kk < 4; kk++) {
            uint32_t ph[4], pl[4];
            {
                float e0 = s[2 * kk][0], e1 = s[2 * kk][1];
                ph[0] = pkbf2(e0, e1);
                pl[0] = pkbf2(e0 - __uint_as_float(ph[0] << 16),
                              e1 - __uint_as_float(ph[0] & 0xffff0000u));
                e0 = s[2 * kk][2]; e1 = s[2 * kk][3];
                ph[1] = pkbf2(e0, e1);
                pl[1] = pkbf2(e0 - __uint_as_float(ph[1] << 16),
                              e1 - __uint_as_float(ph[1] & 0xffff0000u));
                e0 = s[2 * kk + 1][0]; e1 = s[2 * kk + 1][1];
                ph[2] = pkbf2(e0, e1);
                pl[2] = pkbf2(e0 - __uint_as_float(ph[2] << 16),
                              e1 - __uint_as_float(ph[2] & 0xffff0000u));
                e0 = s[2 * kk + 1][2]; e1 = s[2 * kk + 1][3];
                ph[3] = pkbf2(e0, e1);
                pl[3] = pkbf2(e0 - __uint_as_float(ph[3] << 16),
                              e1 - __uint_as_float(ph[3] & 0xffff0000u));
            }
#pragma unroll
            for (int blk = 0; blk < 2; blk++) {
                uint32_t vb[8][2];
#pragma unroll
                for (int p = 0; p < 4; p++)
                    ldsm4(&vb[2 * p][0], vbase + (blk * 64 + p * 16) * 144 + kk * 32);
                // terms ph*vh, pl*vh
#pragma unroll
                for (int j = 0; j < 8; j++) mma_bf16(o[blk * 8 + j], ph, vb[j]);
#pragma unroll
                for (int j = 0; j < 8; j++) mma_bf16(o[blk * 8 + j], pl, vb[j]);
                // reload buffer with V_lo, term ph*vl
#pragma unroll
                for (int p = 0; p < 4; p++)
                    ldsm4(&vb[2 * p][0], vbase + (AV_L - AV_H) +
                                          (blk * 64 + p * 16) * 144 + kk * 32);
#pragma unroll
                for (int j = 0; j < 8; j++) mma_bf16(o[blk * 8 + j], ph, vb[j]);
            }
        }
    }

    // ---- epilogue: y = O / l, split to bf16 hi/lo ----
    float i0 = 1.f / l0, i1 = 1.f / l1;
    size_t row0 = (size_t)b * Tn + qb * 128 + wid * 16 + lg;
#pragma unroll
    for (int nt = 0; nt < 16; nt++) {
        int col = h * 128 + nt * 8 + tq * 2;
        float v0 = o[nt][0] * i0, v1 = o[nt][1] * i0;
        uint32_t hh = pkbf2(v0, v1);
        uint32_t ll = pkbf2(v0 - __uint_as_float(hh << 16),
                            v1 - __uint_as_float(hh & 0xffff0000u));
        *(uint32_t*)(g_yh + row0 * Cn + col) = hh;
        *(uint32_t*)(g_yl + row0 * Cn + col) = ll;
        v0 = o[nt][2] * i1; v1 = o[nt][3] * i1;
        hh = pkbf2(v0, v1);
        ll = pkbf2(v0 - __uint_as_float(hh << 16),
                   v1 - __uint_as_float(hh & 0xffff0000u));
        *(uint32_t*)(g_yh + (row0 + 8) * Cn + col) = hh;
        *(uint32_t*)(g_yl + (row0 + 8) * Cn + col) = ll;
    }
}

// ---------------------------------------------------------------------------
extern "C" void kernel_launch(void* const* d_in, const int* in_sizes, int n_in,
                              void* d_out, int out_size) {
    const float* x      = (const float*)d_in[0];
    const float* cosb   = (const float*)d_in[1];
    const float* sinb   = (const float*)d_in[2];
    const float* w_attn = (const float*)d_in[3];
    const float* w_proj = (const float*)d_in[4];
    float* out = (float*)d_out;
    (void)in_sizes; (void)n_in; (void)out_size;

    (void)cudaFuncSetAttribute(hgemm3_kernel,
                               cudaFuncAttributeMaxDynamicSharedMemorySize, GSM);
    (void)cudaFuncSetAttribute(attn_kernel,
                               cudaFuncAttributeMaxDynamicSharedMemorySize, ATT_SMEM);

    float* qkvp = nullptr;
    bf16 *xh, *xl, *wah, *wal, *wph, *wpl, *yh, *yl;
    (void)cudaGetSymbolAddress((void**)&qkvp, g_qkv);
    (void)cudaGetSymbolAddress((void**)&xh, g_xh);
    (void)cudaGetSymbolAddress((void**)&xl, g_xl);
    (void)cudaGetSymbolAddress((void**)&wah, g_wah);
    (void)cudaGetSymbolAddress((void**)&wal, g_wal);
    (void)cudaGetSymbolAddress((void**)&wph, g_wph);
    (void)cudaGetSymbolAddress((void**)&wpl, g_wpl);
    (void)cudaGetSymbolAddress((void**)&yh, g_yh);
    (void)cudaGetSymbolAddress((void**)&yl, g_yl);

    // 0. splits
    splitx_kernel<<<(ROWS * GK / 4) / 256, 256>>>(x);
    wsplit_kernel<<<dim3(QKVW / 32, GK / 32), dim3(32, 8)>>>(w_attn, wah, wal, QKVW);
    wsplit_kernel<<<dim3(Cn / 32, GK / 32), dim3(32, 8)>>>(w_proj, wph, wpl, Cn);
    // 1. qkv = x @ w_attn
    hgemm3_kernel<<<dim3(QKVW / 128, ROWS / 128), 256, GSM>>>(xh, xl, wah, wal, qkvp, QKVW);
    // 2. RoPE + split q,k
    rope_split_kernel<<<(ROWS * 4 * 5 * 64) / 256, 256>>>(cosb, sinb);
    // 3. v split + transpose
    vsplit_kernel<<<dim3(Tn / 32, 4, 8), dim3(32, 8)>>>();
    // 4. attention -> yh/yl
    attn_kernel<<<dim3(Tn / 128, 16, 2), 256, ATT_SMEM>>>();
    // 5. out = y @ w_proj
    hgemm3_kernel<<<dim3(Cn / 128, ROWS / 128), 256, GSM>>>(yh, yl, wph, wpl, out, Cn);
}